// round 11
// baseline (speedup 1.0000x reference)
#include <cuda_runtime.h>
#include <cuda_bf16.h>
#include <math.h>
#include <stdint.h>

#define RR   1024
#define GG   16
#define DD   1024
#define DGB  64
#define EE   64
#define KFC1 12544

#define SWZ(o) ((o) ^ (((o) >> 3) & 0x70))

__device__ __forceinline__ uint32_t smem_u32(const void* p) {
    uint32_t a;
    asm("{ .reg .u64 t; cvta.to.shared.u64 t, %1; cvt.u32.u64 %0, t; }" : "=r"(a) : "l"(p));
    return a;
}
__device__ __forceinline__ void cpasync16(uint32_t dst, const void* src) {
    asm volatile("cp.async.cg.shared.global [%0], [%1], 16;" :: "r"(dst), "l"(src));
}
__device__ __forceinline__ void ldsm4(uint32_t* r, uint32_t a) {
    asm volatile("ldmatrix.sync.aligned.m8n8.x4.shared.b16 {%0,%1,%2,%3}, [%4];"
                 : "=r"(r[0]), "=r"(r[1]), "=r"(r[2]), "=r"(r[3]) : "r"(a));
}
__device__ __forceinline__ void ldsm2(uint32_t* r, uint32_t a) {
    asm volatile("ldmatrix.sync.aligned.m8n8.x2.shared.b16 {%0,%1}, [%2];"
                 : "=r"(r[0]), "=r"(r[1]) : "r"(a));
}
__device__ __forceinline__ void mma16816(float* c, const uint32_t* a, const uint32_t* b) {
    asm volatile("mma.sync.aligned.m16n8k16.row.col.f32.bf16.bf16.f32 "
                 "{%0,%1,%2,%3}, {%4,%5,%6,%7}, {%8,%9}, {%0,%1,%2,%3};"
                 : "+f"(c[0]), "+f"(c[1]), "+f"(c[2]), "+f"(c[3])
                 : "r"(a[0]), "r"(a[1]), "r"(a[2]), "r"(a[3]), "r"(b[0]), "r"(b[1]));
}
__device__ __forceinline__ void st_hilo(__nv_bfloat16* Chi, __nv_bfloat16* Clo, long off,
                                        float r0, float r1) {
    __nv_bfloat16 h0 = __float2bfloat16(r0), h1 = __float2bfloat16(r1);
    *(__nv_bfloat162*)(Chi + off) = __halves2bfloat162(h0, h1);
    *(__nv_bfloat162*)(Clo + off) = __halves2bfloat162(
        __float2bfloat16(r0 - __bfloat162float(h0)),
        __float2bfloat16(r1 - __bfloat162float(h1)));
}

// ---------------- scratch ----------------
__device__ float g_h[RR*DD];
__device__ float g_B1[(long)RR*GG*RR], g_B2[(long)RR*GG*RR];
__device__ __nv_bfloat16 g_Sh[(long)GG*RR*RR], g_Sl[(long)GG*RR*RR];
__device__ __nv_bfloat16 g_xh[RR*KFC1], g_xl[RR*KFC1];
__device__ __nv_bfloat16 g_w1h[DD*KFC1], g_w1l[DD*KFC1];
__device__ __nv_bfloat16 g_w2h[DD*DD],   g_w2l[DD*DD];
__device__ __nv_bfloat16 g_wq1h[DD*DD], g_wq1l[DD*DD], g_wk1h[DD*DD], g_wk1l[DD*DD];
__device__ __nv_bfloat16 g_wo1h[DD*DD], g_wo1l[DD*DD], g_wa1h[DD*3*DD], g_wa1l[DD*3*DD];
__device__ __nv_bfloat16 g_wq2h[DD*DD], g_wq2l[DD*DD], g_wk2h[DD*DD], g_wk2l[DD*DD];
__device__ __nv_bfloat16 g_wo2h[DD*DD], g_wo2l[DD*DD], g_wa2h[DD*3*DD], g_wa2l[DD*3*DD];
__device__ __nv_bfloat16 g_hh[RR*DD],  g_hl[RR*DD];
__device__ __nv_bfloat16 g_h2h[RR*DD], g_h2l[RR*DD];
__device__ __nv_bfloat16 g_qh[RR*DD],  g_ql[RR*DD];
__device__ __nv_bfloat16 g_kh[RR*DD],  g_kl[RR*DD];
__device__ __nv_bfloat16 g_vth[DD*RR], g_vtl[DD*RR];
__device__ __nv_bfloat16 g_cch[RR*3*DD], g_ccl[RR*3*DD];
__device__ __nv_bfloat16 g_Ph[(long)GG*RR*RR], g_Pl[(long)GG*RR*RR];

// ---------------- position bias ----------------
__global__ __launch_bounds__(128)
void posbias_kernel(const float* __restrict__ pe,
                    const float* __restrict__ Wp1, const float* __restrict__ bp1,
                    const float* __restrict__ Wp2, const float* __restrict__ bp2,
                    float* __restrict__ o1, float* __restrict__ o2)
{
    const int r = blockIdx.x, n = blockIdx.y * 128 + threadIdx.x;
    __shared__ float w1[GG][EE], w2[GG][EE], b1s[GG], b2s[GG];
    for (int i = threadIdx.x; i < GG*EE; i += 128) { w1[i>>6][i&63] = Wp1[i]; w2[i>>6][i&63] = Wp2[i]; }
    if (threadIdx.x < GG) { b1s[threadIdx.x] = bp1[threadIdx.x]; b2s[threadIdx.x] = bp2[threadIdx.x]; }
    __syncthreads();
    float4 pr[EE/4];
    const float4* src = (const float4*)(pe + (((long)r * RR) + n) * EE);
#pragma unroll
    for (int i = 0; i < EE/4; i++) pr[i] = src[i];
#pragma unroll 1
    for (int g = 0; g < GG; ++g) {
        const float4* a = (const float4*)w1[g];
        const float4* b = (const float4*)w2[g];
        float s1 = 0.f, s2 = 0.f;
#pragma unroll
        for (int i = 0; i < EE/4; i++) {
            float4 p = pr[i], xx = a[i], yy = b[i];
            s1 += p.x*xx.x + p.y*xx.y + p.z*xx.z + p.w*xx.w;
            s2 += p.x*yy.x + p.y*yy.y + p.z*yy.z + p.w*yy.w;
        }
        long o = ((long)r * GG + g) * RR + n;
        o1[o] = logf(fmaxf(s1 + b1s[g], 1e-6f));
        o2[o] = logf(fmaxf(s2 + b2s[g], 1e-6f));
    }
}

// ---------------- fp32 -> bf16 hi/lo split ----------------
__global__ __launch_bounds__(256)
void splitk(const float* __restrict__ in, __nv_bfloat16* __restrict__ hi,
            __nv_bfloat16* __restrict__ lo, long n4)
{
    for (long i = (long)blockIdx.x * 256 + threadIdx.x; i < n4; i += (long)gridDim.x * 256) {
        float4 v = ((const float4*)in)[i];
        __nv_bfloat16 a = __float2bfloat16(v.x), b = __float2bfloat16(v.y);
        __nv_bfloat16 c = __float2bfloat16(v.z), d = __float2bfloat16(v.w);
        ((__nv_bfloat162*)hi)[2*i]   = __halves2bfloat162(a, b);
        ((__nv_bfloat162*)hi)[2*i+1] = __halves2bfloat162(c, d);
        ((__nv_bfloat162*)lo)[2*i]   = __halves2bfloat162(
            __float2bfloat16(v.x - __bfloat162float(a)), __float2bfloat16(v.y - __bfloat162float(b)));
        ((__nv_bfloat162*)lo)[2*i+1] = __halves2bfloat162(
            __float2bfloat16(v.z - __bfloat162float(c)), __float2bfloat16(v.w - __bfloat162float(d)));
    }
}

// ---------------- softmax: bf16 hi/lo logits in, bf16 hi/lo probs out ----------------
__global__ __launch_bounds__(256)
void softmax_kernel(const __nv_bfloat16* __restrict__ Sh, const __nv_bfloat16* __restrict__ Sl,
                    const float* __restrict__ bias,
                    __nv_bfloat16* __restrict__ Ph, __nv_bfloat16* __restrict__ Pl)
{
    const int i = blockIdx.x, g = blockIdx.y, tid = threadIdx.x;
    const long base = ((long)g * RR + i) * RR;
    const __nv_bfloat162* sh2 = (const __nv_bfloat162*)(Sh + base);
    const __nv_bfloat162* sl2 = (const __nv_bfloat162*)(Sl + base);
    __nv_bfloat162 a0 = sh2[tid*2], a1 = sh2[tid*2+1];
    __nv_bfloat162 l0 = sl2[tid*2], l1 = sl2[tid*2+1];
    float4 bv = ((const float4*)(bias + ((long)i * GG + g) * RR))[tid];
    float w[4] = {
        __bfloat162float(a0.x) + __bfloat162float(l0.x) + bv.x,
        __bfloat162float(a0.y) + __bfloat162float(l0.y) + bv.y,
        __bfloat162float(a1.x) + __bfloat162float(l1.x) + bv.z,
        __bfloat162float(a1.y) + __bfloat162float(l1.y) + bv.w };
    float mx = fmaxf(fmaxf(w[0], w[1]), fmaxf(w[2], w[3]));
    __shared__ float red[8];
#pragma unroll
    for (int o = 16; o > 0; o >>= 1) mx = fmaxf(mx, __shfl_xor_sync(~0u, mx, o));
    if ((tid & 31) == 0) red[tid >> 5] = mx;
    __syncthreads();
    float m2 = red[0];
#pragma unroll
    for (int k = 1; k < 8; k++) m2 = fmaxf(m2, red[k]);
    float sum = 0.f;
#pragma unroll
    for (int j = 0; j < 4; j++) { w[j] = __expf(w[j] - m2); sum += w[j]; }
#pragma unroll
    for (int o = 16; o > 0; o >>= 1) sum += __shfl_xor_sync(~0u, sum, o);
    __syncthreads();
    if ((tid & 31) == 0) red[tid >> 5] = sum;
    __syncthreads();
    float s2 = 0.f;
#pragma unroll
    for (int k = 0; k < 8; k++) s2 += red[k];
    float inv = 1.f / s2;
    long o = base + tid*4;
    st_hilo(Ph, Pl, o,     w[0]*inv, w[1]*inv);
    st_hilo(Ph, Pl, o + 2, w[2]*inv, w[3]*inv);
}

// ---------------- mma.sync split-precision GEMM (3-stage; Round-9 mainloop) ----------------
// Outputs (all optional):
//   C        : fp32 [ldc-strided, + z*cZ]
//   Chi/Clo  : bf16 hi/lo, same layout as C
//   c2h/c2l  : bf16 hi/lo concat buffer (row stride 3072), col = c2base + z*c2zc + n;
//              if hsum != nullptr, also writes (hsum[m, z*c2zc+n] + r) at col + DD.
#define ATB  16384              // 128 x 64 bf16
#define BTB  8192               // 64 x 64 bf16
#define MBUF (2*ATB + 2*BTB)    // 49152: [Ah|Al|Bh|Bl]
#define MSMEM (3*MBUF)          // 147456, 3 stages

__global__ void __launch_bounds__(256)
mmag(const __nv_bfloat16* __restrict__ Ah, const __nv_bfloat16* __restrict__ Al, int lda, long aZ,
     const __nv_bfloat16* __restrict__ Bh, const __nv_bfloat16* __restrict__ Bl, int ldb, long bZ,
     float* __restrict__ C, __nv_bfloat16* __restrict__ Chi, __nv_bfloat16* __restrict__ Clo,
     int ldc, long cZ,
     __nv_bfloat16* __restrict__ c2h, __nv_bfloat16* __restrict__ c2l,
     int c2base, int c2zc, const float* __restrict__ hsum,
     int K, float alpha, const float* __restrict__ bias, long biasZ, int relu)
{
    extern __shared__ __align__(1024) char smem[];
    const uint32_t sb = smem_u32(smem);
    const int tid = threadIdx.x, lane = tid & 31, wid = tid >> 5;
    const int warp_m = wid & 3, warp_n = wid >> 2;       // 4 x 2
    const int m0 = blockIdx.y * 128, n0 = blockIdx.x * 64;
    const long z = blockIdx.z;
    Ah += z * aZ; Al += z * aZ; Bh += z * bZ; Bl += z * bZ;
    const long coff = z * cZ;
    const float* bp = bias ? bias + z * biasZ : nullptr;

    float acc[2][4][4];
#pragma unroll
    for (int i = 0; i < 2; i++)
#pragma unroll
        for (int j = 0; j < 4; j++)
#pragma unroll
            for (int q = 0; q < 4; q++) acc[i][j][q] = 0.f;

    const int nc = K >> 6;

    auto load_chunk = [&](int c, int buf) {
        const int kk = c << 6;
        const uint32_t base = sb + buf * MBUF;
#pragma unroll
        for (int it = 0; it < 4; it++) {
            int idx = tid + it * 256;
            int row = idx >> 3, g = idx & 7;
            uint32_t d = base + SWZ(row*128 + g*16);
            long off = (long)(m0 + row) * lda + kk + g*8;
            cpasync16(d,       Ah + off);
            cpasync16(d + ATB, Al + off);
        }
#pragma unroll
        for (int it = 0; it < 2; it++) {
            int idx = tid + it * 256;
            int row = idx >> 3, g = idx & 7;
            uint32_t d = base + 2*ATB + SWZ(row*128 + g*16);
            long off = (long)(n0 + row) * ldb + kk + g*8;
            cpasync16(d,       Bh + off);
            cpasync16(d + BTB, Bl + off);
        }
        asm volatile("cp.async.commit_group;");
    };

    load_chunk(0, 0);
    if (nc > 1) load_chunk(1, 1);

    const int rA  = warp_m*32 + (lane & 7) + ((lane >> 3) & 1)*8;
    const int cAb = ((lane >> 4) & 1) * 16;
    const int rB  = warp_n*32 + (lane & 7);
    const int cBb = ((lane >> 3) & 1) * 16;

    for (int c = 0; c < nc; c++) {
        if (c + 1 < nc) asm volatile("cp.async.wait_group 1;");
        else            asm volatile("cp.async.wait_group 0;");
        __syncthreads();
        if (c + 2 < nc) load_chunk(c + 2, (c + 2) % 3);

        const uint32_t ab  = sb + (c % 3) * MBUF;
        const uint32_t alb = ab + ATB, bhb = ab + 2*ATB, blb = ab + 2*ATB + BTB;
#pragma unroll
        for (int ks = 0; ks < 4; ks++) {
            uint32_t ah[2][4], al[2][4], bh[4][2], bl[4][2];
#pragma unroll
            for (int i = 0; i < 2; i++) {
                uint32_t o = SWZ((rA + i*16)*128 + ks*32 + cAb);
                ldsm4(ah[i], ab + o);
                ldsm4(al[i], alb + o);
            }
#pragma unroll
            for (int j = 0; j < 4; j++) {
                uint32_t o = SWZ((rB + j*8)*128 + ks*32 + cBb);
                ldsm2(bh[j], bhb + o);
                ldsm2(bl[j], blb + o);
            }
#pragma unroll
            for (int i = 0; i < 2; i++)
#pragma unroll
                for (int j = 0; j < 4; j++) {
                    mma16816(acc[i][j], ah[i], bh[j]);
                    mma16816(acc[i][j], al[i], bh[j]);
                    mma16816(acc[i][j], ah[i], bl[j]);
                }
        }
        __syncthreads();
    }

#pragma unroll
    for (int i = 0; i < 2; i++) {
        int m = m0 + warp_m*32 + i*16 + (lane >> 2);
#pragma unroll
        for (int j = 0; j < 4; j++) {
            int n = n0 + warp_n*32 + j*8 + (lane & 3)*2;
            float b0v = bp ? bp[n] : 0.f, b1v = bp ? bp[n+1] : 0.f;
            float r0 = acc[i][j][0]*alpha + b0v, r1 = acc[i][j][1]*alpha + b1v;
            float r2 = acc[i][j][2]*alpha + b0v, r3 = acc[i][j][3]*alpha + b1v;
            if (relu) { r0=fmaxf(r0,0.f); r1=fmaxf(r1,0.f); r2=fmaxf(r2,0.f); r3=fmaxf(r3,0.f); }
            long o0 = coff + (long)m*ldc + n, o1 = coff + (long)(m+8)*ldc + n;
            if (C) {
                *(float2*)(C + o0) = make_float2(r0, r1);
                *(float2*)(C + o1) = make_float2(r2, r3);
            }
            if (Chi) {
                st_hilo(Chi, Clo, o0, r0, r1);
                st_hilo(Chi, Clo, o1, r2, r3);
            }
            if (c2h) {
                int cn = (int)z * c2zc + n;
                long o2a = (long)m*(3*DD) + c2base + cn;
                long o2b = (long)(m+8)*(3*DD) + c2base + cn;
                st_hilo(c2h, c2l, o2a, r0, r1);
                st_hilo(c2h, c2l, o2b, r2, r3);
                if (hsum) {
                    float ha0 = hsum[(long)m*DD + cn],     ha1 = hsum[(long)m*DD + cn + 1];
                    float hb0 = hsum[(long)(m+8)*DD + cn], hb1 = hsum[(long)(m+8)*DD + cn + 1];
                    st_hilo(c2h, c2l, o2a + DD, r0 + ha0, r1 + ha1);
                    st_hilo(c2h, c2l, o2b + DD, r2 + hb0, r3 + hb1);
                }
            }
        }
    }
}

// ---------------- host orchestration ----------------
static __nv_bfloat16 *xh,*xl,*w1h,*w1l,*w2h,*w2l;
static __nv_bfloat16 *wq1h,*wq1l,*wk1h,*wk1l,*wo1h,*wo1l,*wa1h,*wa1l;
static __nv_bfloat16 *wq2h,*wq2l,*wk2h,*wk2l,*wo2h,*wo2l,*wa2h,*wa2l;
static __nv_bfloat16 *hh,*hl,*h2h,*h2l,*qh,*ql,*kh,*kl,*vth,*vtl,*cch,*ccl,*Ph,*Pl,*Sh,*Sl;
static float *h,*B1,*B2;

static cudaStream_t sA, sB;
static cudaEvent_t EV[12];
static bool g_init = false;

static inline void do_split(const float* s, __nv_bfloat16* hi, __nv_bfloat16* lo, long n,
                            cudaStream_t st) {
    long n4 = n >> 2;
    int grid = (int)((n4 + 255) / 256); if (grid > 4096) grid = 4096;
    splitk<<<grid, 256, 0, st>>>(s, hi, lo, n4);
}

struct BlkW {
    __nv_bfloat16 *qh,*ql,*kh,*kl,*oh,*ol,*ah,*al;
    const float *bq,*bk,*bo,*ba;
    const float* biasLog;
};

static void relation_block(const BlkW& W, float* outC, __nv_bfloat16* outHi, __nv_bfloat16* outLo,
                           cudaEvent_t eH, cudaEvent_t eK, cudaEvent_t eV)
{
    cudaEventRecord(eH, 0);
    cudaStreamWaitEvent(sA, eH, 0);
    cudaStreamWaitEvent(sB, eH, 0);
    mmag<<<dim3(16,8,1),256,MSMEM,0>>>(hh,hl,DD,0, W.qh,W.ql,DD,0,
                                       nullptr,qh,ql, DD,0,
                                       nullptr,nullptr,0,0,nullptr, DD,1.f, W.bq,0,0);
    mmag<<<dim3(16,8,1),256,MSMEM,sA>>>(hh,hl,DD,0, W.kh,W.kl,DD,0,
                                        nullptr,kh,kl, DD,0,
                                        nullptr,nullptr,0,0,nullptr, DD,1.f, W.bk,0,0);
    cudaEventRecord(eK, sA);
    mmag<<<dim3(16,8,1),256,MSMEM,sB>>>(W.oh,W.ol,DD,0, hh,hl,DD,0,
                                        nullptr,vth,vtl, RR,0,
                                        nullptr,nullptr,0,0,nullptr, DD,1.f, nullptr,0,0);
    cudaEventRecord(eV, sB);
    // S[g] = 0.125 * Q_g K_g^T  -> bf16 hi/lo
    cudaStreamWaitEvent(0, eK, 0);
    mmag<<<dim3(16,8,GG),256,MSMEM,0>>>(qh,ql,DD,DGB, kh,kl,DD,DGB,
                                        nullptr,Sh,Sl, RR,(long)RR*RR,
                                        nullptr,nullptr,0,0,nullptr, DGB,0.125f, nullptr,0,0);
    cudaStreamWaitEvent(0, EV[1], 0);
    softmax_kernel<<<dim3(RR,GG),256,0,0>>>(Sh, Sl, W.biasLog, Ph, Pl);
    // AV: writes att part + h+att part of cc directly (no fp32 att, no catsplit)
    cudaStreamWaitEvent(0, eV, 0);
    mmag<<<dim3(1,8,GG),256,MSMEM,0>>>(Ph,Pl,RR,(long)RR*RR, vth,vtl,RR,(long)DGB*RR,
                                       nullptr,nullptr,nullptr, DD,DGB,
                                       cch,ccl, DD,DGB, h, RR,1.f, W.bo,DGB,0);
    // concat GEMM
    mmag<<<dim3(16,8,1),256,MSMEM,0>>>(cch,ccl,3*DD,0, W.ah,W.al,3*DD,0,
                                       outC,outHi,outLo, DD,0,
                                       nullptr,nullptr,0,0,nullptr, 3*DD,1.f, W.ba,0,1);
}

extern "C" void kernel_launch(void* const* d_in, const int* in_sizes, int n_in,
                              void* d_out, int out_size)
{
    const float* x    = (const float*)d_in[0];
    const float* pe   = (const float*)d_in[1];
    const float* Wfc1 = (const float*)d_in[2];  const float* bfc1 = (const float*)d_in[3];
    const float* Wfc2 = (const float*)d_in[4];  const float* bfc2 = (const float*)d_in[5];
    const float* Wp1  = (const float*)d_in[6];  const float* bp1  = (const float*)d_in[7];
    const float* Wq1  = (const float*)d_in[8];  const float* bq1  = (const float*)d_in[9];
    const float* Wk1  = (const float*)d_in[10]; const float* bk1  = (const float*)d_in[11];
    const float* Wo1  = (const float*)d_in[12]; const float* bo1  = (const float*)d_in[13];
    const float* Wa1  = (const float*)d_in[14]; const float* ba1  = (const float*)d_in[15];
    const float* Wp2  = (const float*)d_in[16]; const float* bp2  = (const float*)d_in[17];
    const float* Wq2  = (const float*)d_in[18]; const float* bq2  = (const float*)d_in[19];
    const float* Wk2  = (const float*)d_in[20]; const float* bk2  = (const float*)d_in[21];
    const float* Wo2  = (const float*)d_in[22]; const float* bo2  = (const float*)d_in[23];
    const float* Wa2  = (const float*)d_in[24]; const float* ba2  = (const float*)d_in[25];
    float* out = (float*)d_out;

    if (!g_init) {
        cudaStreamCreateWithFlags(&sA, cudaStreamNonBlocking);
        cudaStreamCreateWithFlags(&sB, cudaStreamNonBlocking);
        for (int i = 0; i < 12; i++) cudaEventCreateWithFlags(&EV[i], cudaEventDisableTiming);
        g_init = true;
    }

    cudaFuncSetAttribute(mmag, cudaFuncAttributeMaxDynamicSharedMemorySize, MSMEM);

    cudaGetSymbolAddress((void**)&h, g_h);
    cudaGetSymbolAddress((void**)&Sh, g_Sh);   cudaGetSymbolAddress((void**)&Sl, g_Sl);
    cudaGetSymbolAddress((void**)&B1, g_B1);   cudaGetSymbolAddress((void**)&B2, g_B2);
    cudaGetSymbolAddress((void**)&xh, g_xh);   cudaGetSymbolAddress((void**)&xl, g_xl);
    cudaGetSymbolAddress((void**)&w1h, g_w1h); cudaGetSymbolAddress((void**)&w1l, g_w1l);
    cudaGetSymbolAddress((void**)&w2h, g_w2h); cudaGetSymbolAddress((void**)&w2l, g_w2l);
    cudaGetSymbolAddress((void**)&wq1h, g_wq1h); cudaGetSymbolAddress((void**)&wq1l, g_wq1l);
    cudaGetSymbolAddress((void**)&wk1h, g_wk1h); cudaGetSymbolAddress((void**)&wk1l, g_wk1l);
    cudaGetSymbolAddress((void**)&wo1h, g_wo1h); cudaGetSymbolAddress((void**)&wo1l, g_wo1l);
    cudaGetSymbolAddress((void**)&wa1h, g_wa1h); cudaGetSymbolAddress((void**)&wa1l, g_wa1l);
    cudaGetSymbolAddress((void**)&wq2h, g_wq2h); cudaGetSymbolAddress((void**)&wq2l, g_wq2l);
    cudaGetSymbolAddress((void**)&wk2h, g_wk2h); cudaGetSymbolAddress((void**)&wk2l, g_wk2l);
    cudaGetSymbolAddress((void**)&wo2h, g_wo2h); cudaGetSymbolAddress((void**)&wo2l, g_wo2l);
    cudaGetSymbolAddress((void**)&wa2h, g_wa2h); cudaGetSymbolAddress((void**)&wa2l, g_wa2l);
    cudaGetSymbolAddress((void**)&hh, g_hh);   cudaGetSymbolAddress((void**)&hl, g_hl);
    cudaGetSymbolAddress((void**)&h2h, g_h2h); cudaGetSymbolAddress((void**)&h2l, g_h2l);
    cudaGetSymbolAddress((void**)&qh, g_qh);   cudaGetSymbolAddress((void**)&ql, g_ql);
    cudaGetSymbolAddress((void**)&kh, g_kh);   cudaGetSymbolAddress((void**)&kl, g_kl);
    cudaGetSymbolAddress((void**)&vth, g_vth); cudaGetSymbolAddress((void**)&vtl, g_vtl);
    cudaGetSymbolAddress((void**)&cch, g_cch); cudaGetSymbolAddress((void**)&ccl, g_ccl);
    cudaGetSymbolAddress((void**)&Ph, g_Ph);   cudaGetSymbolAddress((void**)&Pl, g_Pl);

    // ---- fork ----
    cudaEventRecord(EV[0], 0);
    cudaStreamWaitEvent(sA, EV[0], 0);
    cudaStreamWaitEvent(sB, EV[0], 0);

    // sA: position bias (memory-bound, overlaps fc1)
    posbias_kernel<<<dim3(RR, RR/128), 128, 0, sA>>>(pe, Wp1, bp1, Wp2, bp2, B1, B2);
    cudaEventRecord(EV[1], sA);

    // sB: splits — x+Wfc1 first (fc1 gate), then remaining weights
    do_split(x, xh, xl, (long)RR*KFC1, sB);
    do_split(Wfc1, w1h, w1l, (long)DD*KFC1, sB);
    cudaEventRecord(EV[2], sB);
    do_split(Wq1, wq1h, wq1l, (long)DD*DD, sB);
    do_split(Wk1, wk1h, wk1l, (long)DD*DD, sB);
    do_split(Wo1, wo1h, wo1l, (long)DD*DD, sB);
    do_split(Wa1, wa1h, wa1l, (long)DD*3*DD, sB);
    do_split(Wfc2, w2h, w2l, (long)DD*DD, sB);
    do_split(Wq2, wq2h, wq2l, (long)DD*DD, sB);
    do_split(Wk2, wk2h, wk2l, (long)DD*DD, sB);
    do_split(Wo2, wo2h, wo2l, (long)DD*DD, sB);
    do_split(Wa2, wa2h, wa2l, (long)DD*3*DD, sB);
    cudaEventRecord(EV[3], sB);

    // stream 0: fc1 after x/Wfc1 splits; epilogue also fills cc[:,0:DD]
    cudaStreamWaitEvent(0, EV[2], 0);
    mmag<<<dim3(16,8,1),256,MSMEM,0>>>(xh,xl,KFC1,0, w1h,w1l,KFC1,0,
                                       h,hh,hl, DD,0,
                                       cch,ccl, 0,0,nullptr, KFC1,1.f, bfc1,0,0);

    cudaStreamWaitEvent(0, EV[3], 0);
    cudaStreamWaitEvent(sA, EV[3], 0);
    cudaStreamWaitEvent(sB, EV[3], 0);

    // relation block 1 -> h2 (bf16 only)
    BlkW W1b = { wq1h,wq1l, wk1h,wk1l, wo1h,wo1l, wa1h,wa1l, bq1,bk1,bo1,ba1, B1 };
    relation_block(W1b, nullptr, h2h, h2l, EV[4], EV[5], EV[6]);

    // fc2: h = h2 @ Wfc2^T + bfc2; epilogue refills cc[:,0:DD]
    mmag<<<dim3(16,8,1),256,MSMEM,0>>>(h2h,h2l,DD,0, w2h,w2l,DD,0,
                                       h,hh,hl, DD,0,
                                       cch,ccl, 0,0,nullptr, DD,1.f, bfc2,0,0);

    // relation block 2 -> out (fp32)
    BlkW W2b = { wq2h,wq2l, wk2h,wk2l, wo2h,wo2l, wa2h,wa2l, bq2,bk2,bo2,ba2, B2 };
    relation_block(W2b, out, nullptr, nullptr, EV[7], EV[8], EV[9]);
}

// round 12
// speedup vs baseline: 1.7338x; 1.7338x over previous
#include <cuda_runtime.h>
#include <cuda_bf16.h>
#include <math.h>
#include <stdint.h>

#define RR   1024
#define GG   16
#define DD   1024
#define DGB  64
#define EE   64
#define KFC1 12544

#define SWZ(o) ((o) ^ (((o) >> 3) & 0x70))

__device__ __forceinline__ uint32_t smem_u32(const void* p) {
    uint32_t a;
    asm("{ .reg .u64 t; cvta.to.shared.u64 t, %1; cvt.u32.u64 %0, t; }" : "=r"(a) : "l"(p));
    return a;
}
__device__ __forceinline__ void cpasync16(uint32_t dst, const void* src) {
    asm volatile("cp.async.cg.shared.global [%0], [%1], 16;" :: "r"(dst), "l"(src));
}
__device__ __forceinline__ void ldsm4(uint32_t* r, uint32_t a) {
    asm volatile("ldmatrix.sync.aligned.m8n8.x4.shared.b16 {%0,%1,%2,%3}, [%4];"
                 : "=r"(r[0]), "=r"(r[1]), "=r"(r[2]), "=r"(r[3]) : "r"(a));
}
__device__ __forceinline__ void ldsm2(uint32_t* r, uint32_t a) {
    asm volatile("ldmatrix.sync.aligned.m8n8.x2.shared.b16 {%0,%1}, [%2];"
                 : "=r"(r[0]), "=r"(r[1]) : "r"(a));
}
__device__ __forceinline__ void mma16816(float* c, const uint32_t* a, const uint32_t* b) {
    asm volatile("mma.sync.aligned.m16n8k16.row.col.f32.bf16.bf16.f32 "
                 "{%0,%1,%2,%3}, {%4,%5,%6,%7}, {%8,%9}, {%0,%1,%2,%3};"
                 : "+f"(c[0]), "+f"(c[1]), "+f"(c[2]), "+f"(c[3])
                 : "r"(a[0]), "r"(a[1]), "r"(a[2]), "r"(a[3]), "r"(b[0]), "r"(b[1]));
}
__device__ __forceinline__ void st_hilo(__nv_bfloat16* Chi, __nv_bfloat16* Clo, long off,
                                        float r0, float r1) {
    __nv_bfloat16 h0 = __float2bfloat16(r0), h1 = __float2bfloat16(r1);
    *(__nv_bfloat162*)(Chi + off) = __halves2bfloat162(h0, h1);
    *(__nv_bfloat162*)(Clo + off) = __halves2bfloat162(
        __float2bfloat16(r0 - __bfloat162float(h0)),
        __float2bfloat16(r1 - __bfloat162float(h1)));
}

// ---------------- scratch ----------------
__device__ float g_h[RR*DD], g_att[RR*DD];
__device__ float g_B1[(long)RR*GG*RR], g_B2[(long)RR*GG*RR];
__device__ __nv_bfloat16 g_Sh[(long)GG*RR*RR], g_Sl[(long)GG*RR*RR];
__device__ __nv_bfloat16 g_xh[RR*KFC1], g_xl[RR*KFC1];
__device__ __nv_bfloat16 g_w1h[DD*KFC1], g_w1l[DD*KFC1];
__device__ __nv_bfloat16 g_w2h[DD*DD],   g_w2l[DD*DD];
__device__ __nv_bfloat16 g_wq1h[DD*DD], g_wq1l[DD*DD], g_wk1h[DD*DD], g_wk1l[DD*DD];
__device__ __nv_bfloat16 g_wo1h[DD*DD], g_wo1l[DD*DD], g_wa1h[DD*3*DD], g_wa1l[DD*3*DD];
__device__ __nv_bfloat16 g_wq2h[DD*DD], g_wq2l[DD*DD], g_wk2h[DD*DD], g_wk2l[DD*DD];
__device__ __nv_bfloat16 g_wo2h[DD*DD], g_wo2l[DD*DD], g_wa2h[DD*3*DD], g_wa2l[DD*3*DD];
__device__ __nv_bfloat16 g_hh[RR*DD],  g_hl[RR*DD];
__device__ __nv_bfloat16 g_h2h[RR*DD], g_h2l[RR*DD];
__device__ __nv_bfloat16 g_qh[RR*DD],  g_ql[RR*DD];
__device__ __nv_bfloat16 g_kh[RR*DD],  g_kl[RR*DD];
__device__ __nv_bfloat16 g_vth[DD*RR], g_vtl[DD*RR];
__device__ __nv_bfloat16 g_cch[RR*3*DD], g_ccl[RR*3*DD];
__device__ __nv_bfloat16 g_Ph[(long)GG*RR*RR], g_Pl[(long)GG*RR*RR];

// ---------------- position bias ----------------
__global__ __launch_bounds__(128)
void posbias_kernel(const float* __restrict__ pe,
                    const float* __restrict__ Wp1, const float* __restrict__ bp1,
                    const float* __restrict__ Wp2, const float* __restrict__ bp2,
                    float* __restrict__ o1, float* __restrict__ o2)
{
    const int r = blockIdx.x, n = blockIdx.y * 128 + threadIdx.x;
    __shared__ float w1[GG][EE], w2[GG][EE], b1s[GG], b2s[GG];
    for (int i = threadIdx.x; i < GG*EE; i += 128) { w1[i>>6][i&63] = Wp1[i]; w2[i>>6][i&63] = Wp2[i]; }
    if (threadIdx.x < GG) { b1s[threadIdx.x] = bp1[threadIdx.x]; b2s[threadIdx.x] = bp2[threadIdx.x]; }
    __syncthreads();
    float4 pr[EE/4];
    const float4* src = (const float4*)(pe + (((long)r * RR) + n) * EE);
#pragma unroll
    for (int i = 0; i < EE/4; i++) pr[i] = src[i];
#pragma unroll 1
    for (int g = 0; g < GG; ++g) {
        const float4* a = (const float4*)w1[g];
        const float4* b = (const float4*)w2[g];
        float s1 = 0.f, s2 = 0.f;
#pragma unroll
        for (int i = 0; i < EE/4; i++) {
            float4 p = pr[i], xx = a[i], yy = b[i];
            s1 += p.x*xx.x + p.y*xx.y + p.z*xx.z + p.w*xx.w;
            s2 += p.x*yy.x + p.y*yy.y + p.z*yy.z + p.w*yy.w;
        }
        long o = ((long)r * GG + g) * RR + n;
        o1[o] = logf(fmaxf(s1 + b1s[g], 1e-6f));
        o2[o] = logf(fmaxf(s2 + b2s[g], 1e-6f));
    }
}

// ---------------- fp32 -> bf16 hi/lo split ----------------
__global__ __launch_bounds__(256)
void splitk(const float* __restrict__ in, __nv_bfloat16* __restrict__ hi,
            __nv_bfloat16* __restrict__ lo, long n4)
{
    for (long i = (long)blockIdx.x * 256 + threadIdx.x; i < n4; i += (long)gridDim.x * 256) {
        float4 v = ((const float4*)in)[i];
        __nv_bfloat16 a = __float2bfloat16(v.x), b = __float2bfloat16(v.y);
        __nv_bfloat16 c = __float2bfloat16(v.z), d = __float2bfloat16(v.w);
        ((__nv_bfloat162*)hi)[2*i]   = __halves2bfloat162(a, b);
        ((__nv_bfloat162*)hi)[2*i+1] = __halves2bfloat162(c, d);
        ((__nv_bfloat162*)lo)[2*i]   = __halves2bfloat162(
            __float2bfloat16(v.x - __bfloat162float(a)), __float2bfloat16(v.y - __bfloat162float(b)));
        ((__nv_bfloat162*)lo)[2*i+1] = __halves2bfloat162(
            __float2bfloat16(v.z - __bfloat162float(c)), __float2bfloat16(v.w - __bfloat162float(d)));
    }
}

// virtual concat [h | a | h+a] -> bf16 hi/lo
__global__ __launch_bounds__(256)
void catsplit(const float* __restrict__ h, const float* __restrict__ a,
              __nv_bfloat16* __restrict__ hi, __nv_bfloat16* __restrict__ lo)
{
    long i = (long)blockIdx.x * 256 + threadIdx.x;
    long e = i * 4;
    int r = (int)(e / (3*DD)), c = (int)(e % (3*DD));
    float4 v;
    if (c < DD) v = *(const float4*)(h + (long)r*DD + c);
    else if (c < 2*DD) v = *(const float4*)(a + (long)r*DD + c - DD);
    else {
        float4 x = *(const float4*)(h + (long)r*DD + c - 2*DD);
        float4 y = *(const float4*)(a + (long)r*DD + c - 2*DD);
        v = make_float4(x.x+y.x, x.y+y.y, x.z+y.z, x.w+y.w);
    }
    __nv_bfloat16 a0 = __float2bfloat16(v.x), b0 = __float2bfloat16(v.y);
    __nv_bfloat16 c0 = __float2bfloat16(v.z), d0 = __float2bfloat16(v.w);
    ((__nv_bfloat162*)hi)[2*i]   = __halves2bfloat162(a0, b0);
    ((__nv_bfloat162*)hi)[2*i+1] = __halves2bfloat162(c0, d0);
    ((__nv_bfloat162*)lo)[2*i]   = __halves2bfloat162(
        __float2bfloat16(v.x - __bfloat162float(a0)), __float2bfloat16(v.y - __bfloat162float(b0)));
    ((__nv_bfloat162*)lo)[2*i+1] = __halves2bfloat162(
        __float2bfloat16(v.z - __bfloat162float(c0)), __float2bfloat16(v.w - __bfloat162float(d0)));
}

// ---------------- softmax: bf16 hi/lo logits in, bf16 hi/lo probs out ----------------
__global__ __launch_bounds__(256)
void softmax_kernel(const __nv_bfloat16* __restrict__ Sh, const __nv_bfloat16* __restrict__ Sl,
                    const float* __restrict__ bias,
                    __nv_bfloat16* __restrict__ Ph, __nv_bfloat16* __restrict__ Pl)
{
    const int i = blockIdx.x, g = blockIdx.y, tid = threadIdx.x;
    const long base = ((long)g * RR + i) * RR;
    const __nv_bfloat162* sh2 = (const __nv_bfloat162*)(Sh + base);
    const __nv_bfloat162* sl2 = (const __nv_bfloat162*)(Sl + base);
    __nv_bfloat162 a0 = sh2[tid*2], a1 = sh2[tid*2+1];
    __nv_bfloat162 l0 = sl2[tid*2], l1 = sl2[tid*2+1];
    float4 bv = ((const float4*)(bias + ((long)i * GG + g) * RR))[tid];
    float w[4] = {
        __bfloat162float(a0.x) + __bfloat162float(l0.x) + bv.x,
        __bfloat162float(a0.y) + __bfloat162float(l0.y) + bv.y,
        __bfloat162float(a1.x) + __bfloat162float(l1.x) + bv.z,
        __bfloat162float(a1.y) + __bfloat162float(l1.y) + bv.w };
    float mx = fmaxf(fmaxf(w[0], w[1]), fmaxf(w[2], w[3]));
    __shared__ float red[8];
#pragma unroll
    for (int o = 16; o > 0; o >>= 1) mx = fmaxf(mx, __shfl_xor_sync(~0u, mx, o));
    if ((tid & 31) == 0) red[tid >> 5] = mx;
    __syncthreads();
    float m2 = red[0];
#pragma unroll
    for (int k = 1; k < 8; k++) m2 = fmaxf(m2, red[k]);
    float sum = 0.f;
#pragma unroll
    for (int j = 0; j < 4; j++) { w[j] = __expf(w[j] - m2); sum += w[j]; }
#pragma unroll
    for (int o = 16; o > 0; o >>= 1) sum += __shfl_xor_sync(~0u, sum, o);
    __syncthreads();
    if ((tid & 31) == 0) red[tid >> 5] = sum;
    __syncthreads();
    float s2 = 0.f;
#pragma unroll
    for (int k = 0; k < 8; k++) s2 += red[k];
    float inv = 1.f / s2;
    long o = base + tid*4;
    st_hilo(Ph, Pl, o,     w[0]*inv, w[1]*inv);
    st_hilo(Ph, Pl, o + 2, w[2]*inv, w[3]*inv);
}

// ---------------- mma.sync split-precision GEMM (3-stage; R9 mainloop; templated epilogue) ----------------
#define ATB  16384              // 128 x 64 bf16
#define BTB  8192               // 64 x 64 bf16
#define MBUF (2*ATB + 2*BTB)    // 49152: [Ah|Al|Bh|Bl]
#define MSMEM (3*MBUF)          // 147456, 3 stages

template<bool HASC, bool HASB>
__global__ void __launch_bounds__(256)
mmag(const __nv_bfloat16* __restrict__ Ah, const __nv_bfloat16* __restrict__ Al, int lda, long aZ,
     const __nv_bfloat16* __restrict__ Bh, const __nv_bfloat16* __restrict__ Bl, int ldb, long bZ,
     float* __restrict__ C, __nv_bfloat16* __restrict__ Chi, __nv_bfloat16* __restrict__ Clo,
     int ldc, long cZ,
     int K, float alpha, const float* __restrict__ bias, long biasZ, int relu)
{
    extern __shared__ __align__(1024) char smem[];
    const uint32_t sb = smem_u32(smem);
    const int tid = threadIdx.x, lane = tid & 31, wid = tid >> 5;
    const int warp_m = wid & 3, warp_n = wid >> 2;       // 4 x 2
    const int m0 = blockIdx.y * 128, n0 = blockIdx.x * 64;
    const long z = blockIdx.z;
    Ah += z * aZ; Al += z * aZ; Bh += z * bZ; Bl += z * bZ;
    const long coff = z * cZ;
    const float* bp = bias ? bias + z * biasZ : nullptr;

    float acc[2][4][4];
#pragma unroll
    for (int i = 0; i < 2; i++)
#pragma unroll
        for (int j = 0; j < 4; j++)
#pragma unroll
            for (int q = 0; q < 4; q++) acc[i][j][q] = 0.f;

    const int nc = K >> 6;

    auto load_chunk = [&](int c, int buf) {
        const int kk = c << 6;
        const uint32_t base = sb + buf * MBUF;
#pragma unroll
        for (int it = 0; it < 4; it++) {
            int idx = tid + it * 256;
            int row = idx >> 3, g = idx & 7;
            uint32_t d = base + SWZ(row*128 + g*16);
            long off = (long)(m0 + row) * lda + kk + g*8;
            cpasync16(d,       Ah + off);
            cpasync16(d + ATB, Al + off);
        }
#pragma unroll
        for (int it = 0; it < 2; it++) {
            int idx = tid + it * 256;
            int row = idx >> 3, g = idx & 7;
            uint32_t d = base + 2*ATB + SWZ(row*128 + g*16);
            long off = (long)(n0 + row) * ldb + kk + g*8;
            cpasync16(d,       Bh + off);
            cpasync16(d + BTB, Bl + off);
        }
        asm volatile("cp.async.commit_group;");
    };

    load_chunk(0, 0);
    if (nc > 1) load_chunk(1, 1);

    const int rA  = warp_m*32 + (lane & 7) + ((lane >> 3) & 1)*8;
    const int cAb = ((lane >> 4) & 1) * 16;
    const int rB  = warp_n*32 + (lane & 7);
    const int cBb = ((lane >> 3) & 1) * 16;

    for (int c = 0; c < nc; c++) {
        if (c + 1 < nc) asm volatile("cp.async.wait_group 1;");
        else            asm volatile("cp.async.wait_group 0;");
        __syncthreads();
        if (c + 2 < nc) load_chunk(c + 2, (c + 2) % 3);

        const uint32_t ab  = sb + (c % 3) * MBUF;
        const uint32_t alb = ab + ATB, bhb = ab + 2*ATB, blb = ab + 2*ATB + BTB;
#pragma unroll
        for (int ks = 0; ks < 4; ks++) {
            uint32_t ah[2][4], al[2][4], bh[4][2], bl[4][2];
#pragma unroll
            for (int i = 0; i < 2; i++) {
                uint32_t o = SWZ((rA + i*16)*128 + ks*32 + cAb);
                ldsm4(ah[i], ab + o);
                ldsm4(al[i], alb + o);
            }
#pragma unroll
            for (int j = 0; j < 4; j++) {
                uint32_t o = SWZ((rB + j*8)*128 + ks*32 + cBb);
                ldsm2(bh[j], bhb + o);
                ldsm2(bl[j], blb + o);
            }
#pragma unroll
            for (int i = 0; i < 2; i++)
#pragma unroll
                for (int j = 0; j < 4; j++) {
                    mma16816(acc[i][j], ah[i], bh[j]);
                    mma16816(acc[i][j], al[i], bh[j]);
                    mma16816(acc[i][j], ah[i], bl[j]);
                }
        }
        __syncthreads();
    }

#pragma unroll
    for (int i = 0; i < 2; i++) {
        int m = m0 + warp_m*32 + i*16 + (lane >> 2);
#pragma unroll
        for (int j = 0; j < 4; j++) {
            int n = n0 + warp_n*32 + j*8 + (lane & 3)*2;
            float b0v = bp ? bp[n] : 0.f, b1v = bp ? bp[n+1] : 0.f;
            float r0 = acc[i][j][0]*alpha + b0v, r1 = acc[i][j][1]*alpha + b1v;
            float r2 = acc[i][j][2]*alpha + b0v, r3 = acc[i][j][3]*alpha + b1v;
            if (relu) { r0=fmaxf(r0,0.f); r1=fmaxf(r1,0.f); r2=fmaxf(r2,0.f); r3=fmaxf(r3,0.f); }
            long o0 = coff + (long)m*ldc + n, o1 = coff + (long)(m+8)*ldc + n;
            if (HASC) {
                *(float2*)(C + o0) = make_float2(r0, r1);
                *(float2*)(C + o1) = make_float2(r2, r3);
            }
            if (HASB) {
                st_hilo(Chi, Clo, o0, r0, r1);
                st_hilo(Chi, Clo, o1, r2, r3);
            }
        }
    }
}

// ---------------- host orchestration ----------------
static __nv_bfloat16 *xh,*xl,*w1h,*w1l,*w2h,*w2l;
static __nv_bfloat16 *wq1h,*wq1l,*wk1h,*wk1l,*wo1h,*wo1l,*wa1h,*wa1l;
static __nv_bfloat16 *wq2h,*wq2l,*wk2h,*wk2l,*wo2h,*wo2l,*wa2h,*wa2l;
static __nv_bfloat16 *hh,*hl,*h2h,*h2l,*qh,*ql,*kh,*kl,*vth,*vtl,*cch,*ccl,*Ph,*Pl,*Sh,*Sl;
static float *h,*att,*B1,*B2;

static cudaStream_t sA, sB;
static cudaEvent_t EV[12];
static bool g_init = false;

static inline void do_split(const float* s, __nv_bfloat16* hi, __nv_bfloat16* lo, long n,
                            cudaStream_t st) {
    long n4 = n >> 2;
    int grid = (int)((n4 + 255) / 256); if (grid > 4096) grid = 4096;
    splitk<<<grid, 256, 0, st>>>(s, hi, lo, n4);
}

struct BlkW {
    __nv_bfloat16 *qh,*ql,*kh,*kl,*oh,*ol,*ah,*al;
    const float *bq,*bk,*bo,*ba;
    const float* biasLog;
};

static void relation_block(const BlkW& W, float* outC, __nv_bfloat16* outHi, __nv_bfloat16* outLo,
                           cudaEvent_t eH, cudaEvent_t eK, cudaEvent_t eV)
{
    cudaEventRecord(eH, 0);
    cudaStreamWaitEvent(sA, eH, 0);
    cudaStreamWaitEvent(sB, eH, 0);
    mmag<false,true><<<dim3(16,8,1),256,MSMEM,0>>>(hh,hl,DD,0, W.qh,W.ql,DD,0,
                                       nullptr,qh,ql, DD,0, DD,1.f, W.bq,0,0);
    mmag<false,true><<<dim3(16,8,1),256,MSMEM,sA>>>(hh,hl,DD,0, W.kh,W.kl,DD,0,
                                        nullptr,kh,kl, DD,0, DD,1.f, W.bk,0,0);
    cudaEventRecord(eK, sA);
    mmag<false,true><<<dim3(16,8,1),256,MSMEM,sB>>>(W.oh,W.ol,DD,0, hh,hl,DD,0,
                                        nullptr,vth,vtl, RR,0, DD,1.f, nullptr,0,0);
    cudaEventRecord(eV, sB);
    // S[g] = 0.125 * Q_g K_g^T  -> bf16 hi/lo
    cudaStreamWaitEvent(0, eK, 0);
    mmag<false,true><<<dim3(16,8,GG),256,MSMEM,0>>>(qh,ql,DD,DGB, kh,kl,DD,DGB,
                                        nullptr,Sh,Sl, RR,(long)RR*RR, DGB,0.125f, nullptr,0,0);
    cudaStreamWaitEvent(0, EV[1], 0);
    softmax_kernel<<<dim3(RR,GG),256,0,0>>>(Sh, Sl, W.biasLog, Ph, Pl);
    cudaStreamWaitEvent(0, eV, 0);
    mmag<true,false><<<dim3(1,8,GG),256,MSMEM,0>>>(Ph,Pl,RR,(long)RR*RR, vth,vtl,RR,(long)DGB*RR,
                                       att,nullptr,nullptr, DD,DGB, RR,1.f, W.bo,DGB,0);
    catsplit<<<(RR*3*DD/4)/256, 256, 0, 0>>>(h, att, cch, ccl);
    if (outC)
        mmag<true,false><<<dim3(16,8,1),256,MSMEM,0>>>(cch,ccl,3*DD,0, W.ah,W.al,3*DD,0,
                                       outC,nullptr,nullptr, DD,0, 3*DD,1.f, W.ba,0,1);
    else
        mmag<false,true><<<dim3(16,8,1),256,MSMEM,0>>>(cch,ccl,3*DD,0, W.ah,W.al,3*DD,0,
                                       nullptr,outHi,outLo, DD,0, 3*DD,1.f, W.ba,0,1);
}

extern "C" void kernel_launch(void* const* d_in, const int* in_sizes, int n_in,
                              void* d_out, int out_size)
{
    const float* x    = (const float*)d_in[0];
    const float* pe   = (const float*)d_in[1];
    const float* Wfc1 = (const float*)d_in[2];  const float* bfc1 = (const float*)d_in[3];
    const float* Wfc2 = (const float*)d_in[4];  const float* bfc2 = (const float*)d_in[5];
    const float* Wp1  = (const float*)d_in[6];  const float* bp1  = (const float*)d_in[7];
    const float* Wq1  = (const float*)d_in[8];  const float* bq1  = (const float*)d_in[9];
    const float* Wk1  = (const float*)d_in[10]; const float* bk1  = (const float*)d_in[11];
    const float* Wo1  = (const float*)d_in[12]; const float* bo1  = (const float*)d_in[13];
    const float* Wa1  = (const float*)d_in[14]; const float* ba1  = (const float*)d_in[15];
    const float* Wp2  = (const float*)d_in[16]; const float* bp2  = (const float*)d_in[17];
    const float* Wq2  = (const float*)d_in[18]; const float* bq2  = (const float*)d_in[19];
    const float* Wk2  = (const float*)d_in[20]; const float* bk2  = (const float*)d_in[21];
    const float* Wo2  = (const float*)d_in[22]; const float* bo2  = (const float*)d_in[23];
    const float* Wa2  = (const float*)d_in[24]; const float* ba2  = (const float*)d_in[25];
    float* out = (float*)d_out;

    if (!g_init) {
        cudaStreamCreateWithFlags(&sA, cudaStreamNonBlocking);
        cudaStreamCreateWithFlags(&sB, cudaStreamNonBlocking);
        for (int i = 0; i < 12; i++) cudaEventCreateWithFlags(&EV[i], cudaEventDisableTiming);
        g_init = true;
    }

    cudaFuncSetAttribute(mmag<true,true>,   cudaFuncAttributeMaxDynamicSharedMemorySize, MSMEM);
    cudaFuncSetAttribute(mmag<false,true>,  cudaFuncAttributeMaxDynamicSharedMemorySize, MSMEM);
    cudaFuncSetAttribute(mmag<true,false>,  cudaFuncAttributeMaxDynamicSharedMemorySize, MSMEM);

    cudaGetSymbolAddress((void**)&h, g_h);     cudaGetSymbolAddress((void**)&att, g_att);
    cudaGetSymbolAddress((void**)&Sh, g_Sh);   cudaGetSymbolAddress((void**)&Sl, g_Sl);
    cudaGetSymbolAddress((void**)&B1, g_B1);   cudaGetSymbolAddress((void**)&B2, g_B2);
    cudaGetSymbolAddress((void**)&xh, g_xh);   cudaGetSymbolAddress((void**)&xl, g_xl);
    cudaGetSymbolAddress((void**)&w1h, g_w1h); cudaGetSymbolAddress((void**)&w1l, g_w1l);
    cudaGetSymbolAddress((void**)&w2h, g_w2h); cudaGetSymbolAddress((void**)&w2l, g_w2l);
    cudaGetSymbolAddress((void**)&wq1h, g_wq1h); cudaGetSymbolAddress((void**)&wq1l, g_wq1l);
    cudaGetSymbolAddress((void**)&wk1h, g_wk1h); cudaGetSymbolAddress((void**)&wk1l, g_wk1l);
    cudaGetSymbolAddress((void**)&wo1h, g_wo1h); cudaGetSymbolAddress((void**)&wo1l, g_wo1l);
    cudaGetSymbolAddress((void**)&wa1h, g_wa1h); cudaGetSymbolAddress((void**)&wa1l, g_wa1l);
    cudaGetSymbolAddress((void**)&wq2h, g_wq2h); cudaGetSymbolAddress((void**)&wq2l, g_wq2l);
    cudaGetSymbolAddress((void**)&wk2h, g_wk2h); cudaGetSymbolAddress((void**)&wk2l, g_wk2l);
    cudaGetSymbolAddress((void**)&wo2h, g_wo2h); cudaGetSymbolAddress((void**)&wo2l, g_wo2l);
    cudaGetSymbolAddress((void**)&wa2h, g_wa2h); cudaGetSymbolAddress((void**)&wa2l, g_wa2l);
    cudaGetSymbolAddress((void**)&hh, g_hh);   cudaGetSymbolAddress((void**)&hl, g_hl);
    cudaGetSymbolAddress((void**)&h2h, g_h2h); cudaGetSymbolAddress((void**)&h2l, g_h2l);
    cudaGetSymbolAddress((void**)&qh, g_qh);   cudaGetSymbolAddress((void**)&ql, g_ql);
    cudaGetSymbolAddress((void**)&kh, g_kh);   cudaGetSymbolAddress((void**)&kl, g_kl);
    cudaGetSymbolAddress((void**)&vth, g_vth); cudaGetSymbolAddress((void**)&vtl, g_vtl);
    cudaGetSymbolAddress((void**)&cch, g_cch); cudaGetSymbolAddress((void**)&ccl, g_ccl);
    cudaGetSymbolAddress((void**)&Ph, g_Ph);   cudaGetSymbolAddress((void**)&Pl, g_Pl);

    // ---- fork ----
    cudaEventRecord(EV[0], 0);
    cudaStreamWaitEvent(sA, EV[0], 0);
    cudaStreamWaitEvent(sB, EV[0], 0);

    // sA: position bias (memory-bound, overlaps fc1)
    posbias_kernel<<<dim3(RR, RR/128), 128, 0, sA>>>(pe, Wp1, bp1, Wp2, bp2, B1, B2);
    cudaEventRecord(EV[1], sA);

    // sB: splits — x+Wfc1 first (fc1 gate), then remaining weights
    do_split(x, xh, xl, (long)RR*KFC1, sB);
    do_split(Wfc1, w1h, w1l, (long)DD*KFC1, sB);
    cudaEventRecord(EV[2], sB);
    do_split(Wq1, wq1h, wq1l, (long)DD*DD, sB);
    do_split(Wk1, wk1h, wk1l, (long)DD*DD, sB);
    do_split(Wo1, wo1h, wo1l, (long)DD*DD, sB);
    do_split(Wa1, wa1h, wa1l, (long)DD*3*DD, sB);
    do_split(Wfc2, w2h, w2l, (long)DD*DD, sB);
    do_split(Wq2, wq2h, wq2l, (long)DD*DD, sB);
    do_split(Wk2, wk2h, wk2l, (long)DD*DD, sB);
    do_split(Wo2, wo2h, wo2l, (long)DD*DD, sB);
    do_split(Wa2, wa2h, wa2l, (long)DD*3*DD, sB);
    cudaEventRecord(EV[3], sB);

    // stream 0: fc1 after x/Wfc1 splits
    cudaStreamWaitEvent(0, EV[2], 0);
    mmag<true,true><<<dim3(16,8,1),256,MSMEM,0>>>(xh,xl,KFC1,0, w1h,w1l,KFC1,0,
                                       h,hh,hl, DD,0, KFC1,1.f, bfc1,0,0);

    cudaStreamWaitEvent(0, EV[3], 0);
    cudaStreamWaitEvent(sA, EV[3], 0);
    cudaStreamWaitEvent(sB, EV[3], 0);

    // relation block 1 -> h2 (bf16 only)
    BlkW W1b = { wq1h,wq1l, wk1h,wk1l, wo1h,wo1l, wa1h,wa1l, bq1,bk1,bo1,ba1, B1 };
    relation_block(W1b, nullptr, h2h, h2l, EV[4], EV[5], EV[6]);

    // fc2: h = h2 @ Wfc2^T + bfc2
    mmag<true,true><<<dim3(16,8,1),256,MSMEM,0>>>(h2h,h2l,DD,0, w2h,w2l,DD,0,
                                       h,hh,hl, DD,0, DD,1.f, bfc2,0,0);

    // relation block 2 -> out (fp32)
    BlkW W2b = { wq2h,wq2l, wk2h,wk2l, wo2h,wo2l, wa2h,wa2l, bq2,bk2,bo2,ba2, B2 };
    relation_block(W2b, out, nullptr, nullptr, EV[7], EV[8], EV[9]);
}

// round 14
// speedup vs baseline: 1.7808x; 1.0271x over previous
#include <cuda_runtime.h>
#include <cuda_bf16.h>
#include <math.h>
#include <stdint.h>

#define RR   1024
#define GG   16
#define DD   1024
#define DGB  64
#define EE   64
#define KFC1 12544

#define SWZ(o) ((o) ^ (((o) >> 3) & 0x70))

__device__ __forceinline__ uint32_t smem_u32(const void* p) {
    uint32_t a;
    asm("{ .reg .u64 t; cvta.to.shared.u64 t, %1; cvt.u32.u64 %0, t; }" : "=r"(a) : "l"(p));
    return a;
}
__device__ __forceinline__ void cpasync16(uint32_t dst, const void* src) {
    asm volatile("cp.async.cg.shared.global [%0], [%1], 16;" :: "r"(dst), "l"(src));
}
__device__ __forceinline__ void ldsm4(uint32_t* r, uint32_t a) {
    asm volatile("ldmatrix.sync.aligned.m8n8.x4.shared.b16 {%0,%1,%2,%3}, [%4];"
                 : "=r"(r[0]), "=r"(r[1]), "=r"(r[2]), "=r"(r[3]) : "r"(a));
}
__device__ __forceinline__ void mma16816(float* c, const uint32_t* a, const uint32_t* b) {
    asm volatile("mma.sync.aligned.m16n8k16.row.col.f32.bf16.bf16.f32 "
                 "{%0,%1,%2,%3}, {%4,%5,%6,%7}, {%8,%9}, {%0,%1,%2,%3};"
                 : "+f"(c[0]), "+f"(c[1]), "+f"(c[2]), "+f"(c[3])
                 : "r"(a[0]), "r"(a[1]), "r"(a[2]), "r"(a[3]), "r"(b[0]), "r"(b[1]));
}
__device__ __forceinline__ void st_hilo(__nv_bfloat16* Chi, __nv_bfloat16* Clo, long off,
                                        float r0, float r1) {
    __nv_bfloat16 h0 = __float2bfloat16(r0), h1 = __float2bfloat16(r1);
    *(__nv_bfloat162*)(Chi + off) = __halves2bfloat162(h0, h1);
    *(__nv_bfloat162*)(Clo + off) = __halves2bfloat162(
        __float2bfloat16(r0 - __bfloat162float(h0)),
        __float2bfloat16(r1 - __bfloat162float(h1)));
}

// ---------------- scratch ----------------
__device__ float g_h[RR*DD], g_att[RR*DD];
__device__ float g_S[(long)GG*RR*RR];
__device__ float g_B1[(long)RR*GG*RR], g_B2[(long)RR*GG*RR];
__device__ __nv_bfloat16 g_xh[RR*KFC1], g_xl[RR*KFC1];
__device__ __nv_bfloat16 g_w1h[DD*KFC1], g_w1l[DD*KFC1];
__device__ __nv_bfloat16 g_w2h[DD*DD],   g_w2l[DD*DD];
__device__ __nv_bfloat16 g_wq1h[DD*DD], g_wq1l[DD*DD], g_wk1h[DD*DD], g_wk1l[DD*DD];
__device__ __nv_bfloat16 g_wo1h[DD*DD], g_wo1l[DD*DD], g_wa1h[DD*3*DD], g_wa1l[DD*3*DD];
__device__ __nv_bfloat16 g_wq2h[DD*DD], g_wq2l[DD*DD], g_wk2h[DD*DD], g_wk2l[DD*DD];
__device__ __nv_bfloat16 g_wo2h[DD*DD], g_wo2l[DD*DD], g_wa2h[DD*3*DD], g_wa2l[DD*3*DD];
__device__ __nv_bfloat16 g_hh[RR*DD],  g_hl[RR*DD];
__device__ __nv_bfloat16 g_h2h[RR*DD], g_h2l[RR*DD];
__device__ __nv_bfloat16 g_qh[RR*DD],  g_ql[RR*DD];
__device__ __nv_bfloat16 g_kh[RR*DD],  g_kl[RR*DD];
__device__ __nv_bfloat16 g_vth[DD*RR], g_vtl[DD*RR];
__device__ __nv_bfloat16 g_cch[RR*3*DD], g_ccl[RR*3*DD];
__device__ __nv_bfloat16 g_Ph[(long)GG*RR*RR], g_Pl[(long)GG*RR*RR];

// ---------------- position bias ----------------
__global__ __launch_bounds__(128)
void posbias_kernel(const float* __restrict__ pe,
                    const float* __restrict__ Wp1, const float* __restrict__ bp1,
                    const float* __restrict__ Wp2, const float* __restrict__ bp2,
                    float* __restrict__ o1, float* __restrict__ o2)
{
    const int r = blockIdx.x, n = blockIdx.y * 128 + threadIdx.x;
    __shared__ float w1[GG][EE], w2[GG][EE], b1s[GG], b2s[GG];
    for (int i = threadIdx.x; i < GG*EE; i += 128) { w1[i>>6][i&63] = Wp1[i]; w2[i>>6][i&63] = Wp2[i]; }
    if (threadIdx.x < GG) { b1s[threadIdx.x] = bp1[threadIdx.x]; b2s[threadIdx.x] = bp2[threadIdx.x]; }
    __syncthreads();
    float4 pr[EE/4];
    const float4* src = (const float4*)(pe + (((long)r * RR) + n) * EE);
#pragma unroll
    for (int i = 0; i < EE/4; i++) pr[i] = src[i];
#pragma unroll 1
    for (int g = 0; g < GG; ++g) {
        const float4* a = (const float4*)w1[g];
        const float4* b = (const float4*)w2[g];
        float s1 = 0.f, s2 = 0.f;
#pragma unroll
        for (int i = 0; i < EE/4; i++) {
            float4 p = pr[i], xx = a[i], yy = b[i];
            s1 += p.x*xx.x + p.y*xx.y + p.z*xx.z + p.w*xx.w;
            s2 += p.x*yy.x + p.y*yy.y + p.z*yy.z + p.w*yy.w;
        }
        long o = ((long)r * GG + g) * RR + n;
        o1[o] = logf(fmaxf(s1 + b1s[g], 1e-6f));
        o2[o] = logf(fmaxf(s2 + b2s[g], 1e-6f));
    }
}

// ---------------- fp32 -> bf16 hi/lo split ----------------
__global__ __launch_bounds__(256)
void splitk(const float* __restrict__ in, __nv_bfloat16* __restrict__ hi,
            __nv_bfloat16* __restrict__ lo, long n4)
{
    for (long i = (long)blockIdx.x * 256 + threadIdx.x; i < n4; i += (long)gridDim.x * 256) {
        float4 v = ((const float4*)in)[i];
        __nv_bfloat16 a = __float2bfloat16(v.x), b = __float2bfloat16(v.y);
        __nv_bfloat16 c = __float2bfloat16(v.z), d = __float2bfloat16(v.w);
        ((__nv_bfloat162*)hi)[2*i]   = __halves2bfloat162(a, b);
        ((__nv_bfloat162*)hi)[2*i+1] = __halves2bfloat162(c, d);
        ((__nv_bfloat162*)lo)[2*i]   = __halves2bfloat162(
            __float2bfloat16(v.x - __bfloat162float(a)), __float2bfloat16(v.y - __bfloat162float(b)));
        ((__nv_bfloat162*)lo)[2*i+1] = __halves2bfloat162(
            __float2bfloat16(v.z - __bfloat162float(c)), __float2bfloat16(v.w - __bfloat162float(d)));
    }
}

// virtual concat [h | a | h+a] -> bf16 hi/lo
__global__ __launch_bounds__(256)
void catsplit(const float* __restrict__ h, const float* __restrict__ a,
              __nv_bfloat16* __restrict__ hi, __nv_bfloat16* __restrict__ lo)
{
    long i = (long)blockIdx.x * 256 + threadIdx.x;
    long e = i * 4;
    int r = (int)(e / (3*DD)), c = (int)(e % (3*DD));
    float4 v;
    if (c < DD) v = *(const float4*)(h + (long)r*DD + c);
    else if (c < 2*DD) v = *(const float4*)(a + (long)r*DD + c - DD);
    else {
        float4 x = *(const float4*)(h + (long)r*DD + c - 2*DD);
        float4 y = *(const float4*)(a + (long)r*DD + c - 2*DD);
        v = make_float4(x.x+y.x, x.y+y.y, x.z+y.z, x.w+y.w);
    }
    __nv_bfloat16 a0 = __float2bfloat16(v.x), b0 = __float2bfloat16(v.y);
    __nv_bfloat16 c0 = __float2bfloat16(v.z), d0 = __float2bfloat16(v.w);
    ((__nv_bfloat162*)hi)[2*i]   = __halves2bfloat162(a0, b0);
    ((__nv_bfloat162*)hi)[2*i+1] = __halves2bfloat162(c0, d0);
    ((__nv_bfloat162*)lo)[2*i]   = __halves2bfloat162(
        __float2bfloat16(v.x - __bfloat162float(a0)), __float2bfloat16(v.y - __bfloat162float(b0)));
    ((__nv_bfloat162*)lo)[2*i+1] = __halves2bfloat162(
        __float2bfloat16(v.z - __bfloat162float(c0)), __float2bfloat16(v.w - __bfloat162float(d0)));
}

// ---------------- softmax: fp32 in, bf16 hi/lo out ----------------
__global__ __launch_bounds__(256)
void softmax_kernel(const float* __restrict__ S, const float* __restrict__ bias,
                    __nv_bfloat16* __restrict__ Ph, __nv_bfloat16* __restrict__ Pl)
{
    const int i = blockIdx.x, g = blockIdx.y, tid = threadIdx.x;
    const long base = ((long)g * RR + i) * RR;
    float4 rv = ((const float4*)(S + base))[tid];
    float4 bv = ((const float4*)(bias + ((long)i * GG + g) * RR))[tid];
    float w[4] = { rv.x + bv.x, rv.y + bv.y, rv.z + bv.z, rv.w + bv.w };
    float mx = fmaxf(fmaxf(w[0], w[1]), fmaxf(w[2], w[3]));
    __shared__ float red[8];
#pragma unroll
    for (int o = 16; o > 0; o >>= 1) mx = fmaxf(mx, __shfl_xor_sync(~0u, mx, o));
    if ((tid & 31) == 0) red[tid >> 5] = mx;
    __syncthreads();
    float m2 = red[0];
#pragma unroll
    for (int k = 1; k < 8; k++) m2 = fmaxf(m2, red[k]);
    float sum = 0.f;
#pragma unroll
    for (int j = 0; j < 4; j++) { w[j] = __expf(w[j] - m2); sum += w[j]; }
#pragma unroll
    for (int o = 16; o > 0; o >>= 1) sum += __shfl_xor_sync(~0u, sum, o);
    __syncthreads();
    if ((tid & 31) == 0) red[tid >> 5] = sum;
    __syncthreads();
    float s2 = 0.f;
#pragma unroll
    for (int k = 0; k < 8; k++) s2 += red[k];
    float inv = 1.f / s2;
    long o = base + tid*4;
    st_hilo(Ph, Pl, o,     w[0]*inv, w[1]*inv);
    st_hilo(Ph, Pl, o + 2, w[2]*inv, w[3]*inv);
}

// ---------------- mma.sync split-precision GEMM ----------------
// 3-stage cp.async; B fragments via paired ldsm4 (lanes 16-31 address block j+1).
#define ATB  16384              // 128 x 64 bf16
#define BTB  8192               // 64 x 64 bf16
#define MBUF (2*ATB + 2*BTB)    // 49152: [Ah|Al|Bh|Bl]
#define MSMEM (3*MBUF)          // 147456, 3 stages

template<bool HASC, bool HASB>
__global__ void __launch_bounds__(256)
mmag(const __nv_bfloat16* __restrict__ Ah, const __nv_bfloat16* __restrict__ Al, int lda, long aZ,
     const __nv_bfloat16* __restrict__ Bh, const __nv_bfloat16* __restrict__ Bl, int ldb, long bZ,
     float* __restrict__ C, __nv_bfloat16* __restrict__ Chi, __nv_bfloat16* __restrict__ Clo,
     int ldc, long cZ,
     int K, float alpha, const float* __restrict__ bias, long biasZ, int relu)
{
    extern __shared__ __align__(1024) char smem[];
    const uint32_t sb = smem_u32(smem);
    const int tid = threadIdx.x, lane = tid & 31, wid = tid >> 5;
    const int warp_m = wid & 3, warp_n = wid >> 2;       // 4 x 2
    const int m0 = blockIdx.y * 128, n0 = blockIdx.x * 64;
    const long z = blockIdx.z;
    Ah += z * aZ; Al += z * aZ; Bh += z * bZ; Bl += z * bZ;
    const long coff = z * cZ;
    const float* bp = bias ? bias + z * biasZ : nullptr;

    float acc[2][4][4];
#pragma unroll
    for (int i = 0; i < 2; i++)
#pragma unroll
        for (int j = 0; j < 4; j++)
#pragma unroll
            for (int q = 0; q < 4; q++) acc[i][j][q] = 0.f;

    const int nc = K >> 6;

    auto load_chunk = [&](int c, int buf) {
        const int kk = c << 6;
        const uint32_t base = sb + buf * MBUF;
#pragma unroll
        for (int it = 0; it < 4; it++) {
            int idx = tid + it * 256;
            int row = idx >> 3, g = idx & 7;
            uint32_t d = base + SWZ(row*128 + g*16);
            long off = (long)(m0 + row) * lda + kk + g*8;
            cpasync16(d,       Ah + off);
            cpasync16(d + ATB, Al + off);
        }
#pragma unroll
        for (int it = 0; it < 2; it++) {
            int idx = tid + it * 256;
            int row = idx >> 3, g = idx & 7;
            uint32_t d = base + 2*ATB + SWZ(row*128 + g*16);
            long off = (long)(n0 + row) * ldb + kk + g*8;
            cpasync16(d,       Bh + off);
            cpasync16(d + BTB, Bl + off);
        }
        asm volatile("cp.async.commit_group;");
    };

    load_chunk(0, 0);
    if (nc > 1) load_chunk(1, 1);

    const int rA  = warp_m*32 + (lane & 7) + ((lane >> 3) & 1)*8;   // + i*16
    const int cAb = ((lane >> 4) & 1) * 16;                          // + ks*32
    // B paired ldsm4: lanes 0-15 -> block 2*j2 (k-lo/k-hi), lanes 16-31 -> block 2*j2+1
    const int rB4 = warp_n*32 + ((lane >> 4) & 1)*8 + (lane & 7);    // + j2*16
    const int cBb = ((lane >> 3) & 1) * 16;                          // + ks*32

    for (int c = 0; c < nc; c++) {
        if (c + 1 < nc) asm volatile("cp.async.wait_group 1;");
        else            asm volatile("cp.async.wait_group 0;");
        __syncthreads();
        if (c + 2 < nc) load_chunk(c + 2, (c + 2) % 3);

        const uint32_t ab  = sb + (c % 3) * MBUF;
        const uint32_t alb = ab + ATB, bhb = ab + 2*ATB, blb = ab + 2*ATB + BTB;
#pragma unroll
        for (int ks = 0; ks < 4; ks++) {
            uint32_t ah[2][4], al[2][4], bh[4][2], bl[4][2];
#pragma unroll
            for (int i = 0; i < 2; i++) {
                uint32_t o = SWZ((rA + i*16)*128 + ks*32 + cAb);
                ldsm4(ah[i], ab + o);
                ldsm4(al[i], alb + o);
            }
#pragma unroll
            for (int j2 = 0; j2 < 2; j2++) {
                uint32_t o = SWZ((rB4 + j2*16)*128 + ks*32 + cBb);
                ldsm4(&bh[2*j2][0], bhb + o);
                ldsm4(&bl[2*j2][0], blb + o);
            }
#pragma unroll
            for (int i = 0; i < 2; i++)
#pragma unroll
                for (int j = 0; j < 4; j++) {
                    mma16816(acc[i][j], ah[i], bh[j]);
                    mma16816(acc[i][j], al[i], bh[j]);
                    mma16816(acc[i][j], ah[i], bl[j]);
                }
        }
        __syncthreads();
    }

#pragma unroll
    for (int i = 0; i < 2; i++) {
        int m = m0 + warp_m*32 + i*16 + (lane >> 2);
#pragma unroll
        for (int j = 0; j < 4; j++) {
            int n = n0 + warp_n*32 + j*8 + (lane & 3)*2;
            float b0v = bp ? bp[n] : 0.f, b1v = bp ? bp[n+1] : 0.f;
            float r0 = acc[i][j][0]*alpha + b0v, r1 = acc[i][j][1]*alpha + b1v;
            float r2 = acc[i][j][2]*alpha + b0v, r3 = acc[i][j][3]*alpha + b1v;
            if (relu) { r0=fmaxf(r0,0.f); r1=fmaxf(r1,0.f); r2=fmaxf(r2,0.f); r3=fmaxf(r3,0.f); }
            long o0 = coff + (long)m*ldc + n, o1 = coff + (long)(m+8)*ldc + n;
            if (HASC) {
                *(float2*)(C + o0) = make_float2(r0, r1);
                *(float2*)(C + o1) = make_float2(r2, r3);
            }
            if (HASB) {
                st_hilo(Chi, Clo, o0, r0, r1);
                st_hilo(Chi, Clo, o1, r2, r3);
            }
        }
    }
}

// ---------------- host orchestration ----------------
static __nv_bfloat16 *xh,*xl,*w1h,*w1l,*w2h,*w2l;
static __nv_bfloat16 *wq1h,*wq1l,*wk1h,*wk1l,*wo1h,*wo1l,*wa1h,*wa1l;
static __nv_bfloat16 *wq2h,*wq2l,*wk2h,*wk2l,*wo2h,*wo2l,*wa2h,*wa2l;
static __nv_bfloat16 *hh,*hl,*h2h,*h2l,*qh,*ql,*kh,*kl,*vth,*vtl,*cch,*ccl,*Ph,*Pl;
static float *h,*att,*S,*B1,*B2;

static cudaStream_t sA, sB;
static cudaEvent_t EV[12];
static bool g_init = false;

static inline void do_split(const float* s, __nv_bfloat16* hi, __nv_bfloat16* lo, long n,
                            cudaStream_t st) {
    long n4 = n >> 2;
    int grid = (int)((n4 + 255) / 256); if (grid > 4096) grid = 4096;
    splitk<<<grid, 256, 0, st>>>(s, hi, lo, n4);
}

struct BlkW {
    __nv_bfloat16 *qh,*ql,*kh,*kl,*oh,*ol,*ah,*al;
    const float *bq,*bk,*bo,*ba;
    const float* biasLog;
};

static void relation_block(const BlkW& W, float* outC, __nv_bfloat16* outHi, __nv_bfloat16* outLo,
                           cudaEvent_t eH, cudaEvent_t eK, cudaEvent_t eV)
{
    cudaEventRecord(eH, 0);
    cudaStreamWaitEvent(sA, eH, 0);
    cudaStreamWaitEvent(sB, eH, 0);
    mmag<false,true><<<dim3(16,8,1),256,MSMEM,0>>>(hh,hl,DD,0, W.qh,W.ql,DD,0,
                                       nullptr,qh,ql, DD,0, DD,1.f, W.bq,0,0);
    mmag<false,true><<<dim3(16,8,1),256,MSMEM,sA>>>(hh,hl,DD,0, W.kh,W.kl,DD,0,
                                        nullptr,kh,kl, DD,0, DD,1.f, W.bk,0,0);
    cudaEventRecord(eK, sA);
    mmag<false,true><<<dim3(16,8,1),256,MSMEM,sB>>>(W.oh,W.ol,DD,0, hh,hl,DD,0,
                                        nullptr,vth,vtl, RR,0, DD,1.f, nullptr,0,0);
    cudaEventRecord(eV, sB);
    // S[g] = 0.125 * Q_g K_g^T  (fp32)
    cudaStreamWaitEvent(0, eK, 0);
    mmag<true,false><<<dim3(16,8,GG),256,MSMEM,0>>>(qh,ql,DD,DGB, kh,kl,DD,DGB,
                                        S,nullptr,nullptr, RR,(long)RR*RR, DGB,0.125f, nullptr,0,0);
    cudaStreamWaitEvent(0, EV[1], 0);
    softmax_kernel<<<dim3(RR,GG),256,0,0>>>(S, W.biasLog, Ph, Pl);
    cudaStreamWaitEvent(0, eV, 0);
    mmag<true,false><<<dim3(1,8,GG),256,MSMEM,0>>>(Ph,Pl,RR,(long)RR*RR, vth,vtl,RR,(long)DGB*RR,
                                       att,nullptr,nullptr, DD,DGB, RR,1.f, W.bo,DGB,0);
    catsplit<<<(RR*3*DD/4)/256, 256, 0, 0>>>(h, att, cch, ccl);
    if (outC)
        mmag<true,false><<<dim3(16,8,1),256,MSMEM,0>>>(cch,ccl,3*DD,0, W.ah,W.al,3*DD,0,
                                       outC,nullptr,nullptr, DD,0, 3*DD,1.f, W.ba,0,1);
    else
        mmag<false,true><<<dim3(16,8,1),256,MSMEM,0>>>(cch,ccl,3*DD,0, W.ah,W.al,3*DD,0,
                                       nullptr,outHi,outLo, DD,0, 3*DD,1.f, W.ba,0,1);
}

extern "C" void kernel_launch(void* const* d_in, const int* in_sizes, int n_in,
                              void* d_out, int out_size)
{
    const float* x    = (const float*)d_in[0];
    const float* pe   = (const float*)d_in[1];
    const float* Wfc1 = (const float*)d_in[2];  const float* bfc1 = (const float*)d_in[3];
    const float* Wfc2 = (const float*)d_in[4];  const float* bfc2 = (const float*)d_in[5];
    const float* Wp1  = (const float*)d_in[6];  const float* bp1  = (const float*)d_in[7];
    const float* Wq1  = (const float*)d_in[8];  const float* bq1  = (const float*)d_in[9];
    const float* Wk1  = (const float*)d_in[10]; const float* bk1  = (const float*)d_in[11];
    const float* Wo1  = (const float*)d_in[12]; const float* bo1  = (const float*)d_in[13];
    const float* Wa1  = (const float*)d_in[14]; const float* ba1  = (const float*)d_in[15];
    const float* Wp2  = (const float*)d_in[16]; const float* bp2  = (const float*)d_in[17];
    const float* Wq2  = (const float*)d_in[18]; const float* bq2  = (const float*)d_in[19];
    const float* Wk2  = (const float*)d_in[20]; const float* bk2  = (const float*)d_in[21];
    const float* Wo2  = (const float*)d_in[22]; const float* bo2  = (const float*)d_in[23];
    const float* Wa2  = (const float*)d_in[24]; const float* ba2  = (const float*)d_in[25];
    float* out = (float*)d_out;

    if (!g_init) {
        cudaStreamCreateWithFlags(&sA, cudaStreamNonBlocking);
        cudaStreamCreateWithFlags(&sB, cudaStreamNonBlocking);
        for (int i = 0; i < 12; i++) cudaEventCreateWithFlags(&EV[i], cudaEventDisableTiming);
        g_init = true;
    }

    cudaFuncSetAttribute(mmag<true,true>,   cudaFuncAttributeMaxDynamicSharedMemorySize, MSMEM);
    cudaFuncSetAttribute(mmag<false,true>,  cudaFuncAttributeMaxDynamicSharedMemorySize, MSMEM);
    cudaFuncSetAttribute(mmag<true,false>,  cudaFuncAttributeMaxDynamicSharedMemorySize, MSMEM);

    cudaGetSymbolAddress((void**)&h, g_h);     cudaGetSymbolAddress((void**)&att, g_att);
    cudaGetSymbolAddress((void**)&S, g_S);
    cudaGetSymbolAddress((void**)&B1, g_B1);   cudaGetSymbolAddress((void**)&B2, g_B2);
    cudaGetSymbolAddress((void**)&xh, g_xh);   cudaGetSymbolAddress((void**)&xl, g_xl);
    cudaGetSymbolAddress((void**)&w1h, g_w1h); cudaGetSymbolAddress((void**)&w1l, g_w1l);
    cudaGetSymbolAddress((void**)&w2h, g_w2h); cudaGetSymbolAddress((void**)&w2l, g_w2l);
    cudaGetSymbolAddress((void**)&wq1h, g_wq1h); cudaGetSymbolAddress((void**)&wq1l, g_wq1l);
    cudaGetSymbolAddress((void**)&wk1h, g_wk1h); cudaGetSymbolAddress((void**)&wk1l, g_wk1l);
    cudaGetSymbolAddress((void**)&wo1h, g_wo1h); cudaGetSymbolAddress((void**)&wo1l, g_wo1l);
    cudaGetSymbolAddress((void**)&wa1h, g_wa1h); cudaGetSymbolAddress((void**)&wa1l, g_wa1l);
    cudaGetSymbolAddress((void**)&wq2h, g_wq2h); cudaGetSymbolAddress((void**)&wq2l, g_wq2l);
    cudaGetSymbolAddress((void**)&wk2h, g_wk2h); cudaGetSymbolAddress((void**)&wk2l, g_wk2l);
    cudaGetSymbolAddress((void**)&wo2h, g_wo2h); cudaGetSymbolAddress((void**)&wo2l, g_wo2l);
    cudaGetSymbolAddress((void**)&wa2h, g_wa2h); cudaGetSymbolAddress((void**)&wa2l, g_wa2l);
    cudaGetSymbolAddress((void**)&hh, g_hh);   cudaGetSymbolAddress((void**)&hl, g_hl);
    cudaGetSymbolAddress((void**)&h2h, g_h2h); cudaGetSymbolAddress((void**)&h2l, g_h2l);
    cudaGetSymbolAddress((void**)&qh, g_qh);   cudaGetSymbolAddress((void**)&ql, g_ql);
    cudaGetSymbolAddress((void**)&kh, g_kh);   cudaGetSymbolAddress((void**)&kl, g_kl);
    cudaGetSymbolAddress((void**)&vth, g_vth); cudaGetSymbolAddress((void**)&vtl, g_vtl);
    cudaGetSymbolAddress((void**)&cch, g_cch); cudaGetSymbolAddress((void**)&ccl, g_ccl);
    cudaGetSymbolAddress((void**)&Ph, g_Ph);   cudaGetSymbolAddress((void**)&Pl, g_Pl);

    // ---- fork ----
    cudaEventRecord(EV[0], 0);
    cudaStreamWaitEvent(sA, EV[0], 0);
    cudaStreamWaitEvent(sB, EV[0], 0);

    // sA: position bias (memory-bound, overlaps fc1)
    posbias_kernel<<<dim3(RR, RR/128), 128, 0, sA>>>(pe, Wp1, bp1, Wp2, bp2, B1, B2);
    cudaEventRecord(EV[1], sA);

    // sB: splits — x+Wfc1 first (fc1 gate), then remaining weights
    do_split(x, xh, xl, (long)RR*KFC1, sB);
    do_split(Wfc1, w1h, w1l, (long)DD*KFC1, sB);
    cudaEventRecord(EV[2], sB);
    do_split(Wq1, wq1h, wq1l, (long)DD*DD, sB);
    do_split(Wk1, wk1h, wk1l, (long)DD*DD, sB);
    do_split(Wo1, wo1h, wo1l, (long)DD*DD, sB);
    do_split(Wa1, wa1h, wa1l, (long)DD*3*DD, sB);
    do_split(Wfc2, w2h, w2l, (long)DD*DD, sB);
    do_split(Wq2, wq2h, wq2l, (long)DD*DD, sB);
    do_split(Wk2, wk2h, wk2l, (long)DD*DD, sB);
    do_split(Wo2, wo2h, wo2l, (long)DD*DD, sB);
    do_split(Wa2, wa2h, wa2l, (long)DD*3*DD, sB);
    cudaEventRecord(EV[3], sB);

    // stream 0: fc1 after x/Wfc1 splits
    cudaStreamWaitEvent(0, EV[2], 0);
    mmag<true,true><<<dim3(16,8,1),256,MSMEM,0>>>(xh,xl,KFC1,0, w1h,w1l,KFC1,0,
                                       h,hh,hl, DD,0, KFC1,1.f, bfc1,0,0);

    cudaStreamWaitEvent(0, EV[3], 0);
    cudaStreamWaitEvent(sA, EV[3], 0);
    cudaStreamWaitEvent(sB, EV[3], 0);

    // relation block 1 -> h2 (bf16 only)
    BlkW W1b = { wq1h,wq1l, wk1h,wk1l, wo1h,wo1l, wa1h,wa1l, bq1,bk1,bo1,ba1, B1 };
    relation_block(W1b, nullptr, h2h, h2l, EV[4], EV[5], EV[6]);

    // fc2: h = h2 @ Wfc2^T + bfc2
    mmag<true,true><<<dim3(16,8,1),256,MSMEM,0>>>(h2h,h2l,DD,0, w2h,w2l,DD,0,
                                       h,hh,hl, DD,0, DD,1.f, bfc2,0,0);

    // relation block 2 -> out (fp32)
    BlkW W2b = { wq2h,wq2l, wk2h,wk2l, wo2h,wo2l, wa2h,wa2l, bq2,bk2,bo2,ba2, B2 };
    relation_block(W2b, out, nullptr, nullptr, EV[7], EV[8], EV[9]);
}

// round 15
// speedup vs baseline: 1.9242x; 1.0806x over previous
#include <cuda_runtime.h>
#include <cuda_bf16.h>
#include <math.h>
#include <stdint.h>

#define RR   1024
#define GG   16
#define DD   1024
#define DGB  64
#define EE   64
#define KFC1 12544
#define KHALF 6272

#define SWZ(o) ((o) ^ (((o) >> 3) & 0x70))

__device__ __forceinline__ uint32_t smem_u32(const void* p) {
    uint32_t a;
    asm("{ .reg .u64 t; cvta.to.shared.u64 t, %1; cvt.u32.u64 %0, t; }" : "=r"(a) : "l"(p));
    return a;
}
__device__ __forceinline__ void cpasync16(uint32_t dst, const void* src) {
    asm volatile("cp.async.cg.shared.global [%0], [%1], 16;" :: "r"(dst), "l"(src));
}
__device__ __forceinline__ void ldsm4(uint32_t* r, uint32_t a) {
    asm volatile("ldmatrix.sync.aligned.m8n8.x4.shared.b16 {%0,%1,%2,%3}, [%4];"
                 : "=r"(r[0]), "=r"(r[1]), "=r"(r[2]), "=r"(r[3]) : "r"(a));
}
__device__ __forceinline__ void mma16816(float* c, const uint32_t* a, const uint32_t* b) {
    asm volatile("mma.sync.aligned.m16n8k16.row.col.f32.bf16.bf16.f32 "
                 "{%0,%1,%2,%3}, {%4,%5,%6,%7}, {%8,%9}, {%0,%1,%2,%3};"
                 : "+f"(c[0]), "+f"(c[1]), "+f"(c[2]), "+f"(c[3])
                 : "r"(a[0]), "r"(a[1]), "r"(a[2]), "r"(a[3]), "r"(b[0]), "r"(b[1]));
}
__device__ __forceinline__ void st_hilo(__nv_bfloat16* Chi, __nv_bfloat16* Clo, long off,
                                        float r0, float r1) {
    __nv_bfloat16 h0 = __float2bfloat16(r0), h1 = __float2bfloat16(r1);
    *(__nv_bfloat162*)(Chi + off) = __halves2bfloat162(h0, h1);
    *(__nv_bfloat162*)(Clo + off) = __halves2bfloat162(
        __float2bfloat16(r0 - __bfloat162float(h0)),
        __float2bfloat16(r1 - __bfloat162float(h1)));
}

// ---------------- scratch ----------------
__device__ float g_h[RR*DD], g_att[RR*DD];
__device__ float g_p[2*RR*DD];                       // fc1 split-K partials
__device__ float g_S[(long)GG*RR*RR];
__device__ float g_B1[(long)RR*GG*RR], g_B2[(long)RR*GG*RR];
__device__ __nv_bfloat16 g_xh[RR*KFC1], g_xl[RR*KFC1];
__device__ __nv_bfloat16 g_w1h[DD*KFC1], g_w1l[DD*KFC1];
__device__ __nv_bfloat16 g_w2h[DD*DD],   g_w2l[DD*DD];
__device__ __nv_bfloat16 g_wq1h[DD*DD], g_wq1l[DD*DD], g_wk1h[DD*DD], g_wk1l[DD*DD];
__device__ __nv_bfloat16 g_wo1h[DD*DD], g_wo1l[DD*DD], g_wa1h[DD*3*DD], g_wa1l[DD*3*DD];
__device__ __nv_bfloat16 g_wq2h[DD*DD], g_wq2l[DD*DD], g_wk2h[DD*DD], g_wk2l[DD*DD];
__device__ __nv_bfloat16 g_wo2h[DD*DD], g_wo2l[DD*DD], g_wa2h[DD*3*DD], g_wa2l[DD*3*DD];
__device__ __nv_bfloat16 g_hh[RR*DD],  g_hl[RR*DD];
__device__ __nv_bfloat16 g_h2h[RR*DD], g_h2l[RR*DD];
__device__ __nv_bfloat16 g_qh[RR*DD],  g_ql[RR*DD];
__device__ __nv_bfloat16 g_kh[RR*DD],  g_kl[RR*DD];
__device__ __nv_bfloat16 g_vth[DD*RR], g_vtl[DD*RR];
__device__ __nv_bfloat16 g_cch[RR*3*DD], g_ccl[RR*3*DD];
__device__ __nv_bfloat16 g_Ph[(long)GG*RR*RR], g_Pl[(long)GG*RR*RR];

// ---------------- position bias ----------------
__global__ __launch_bounds__(128)
void posbias_kernel(const float* __restrict__ pe,
                    const float* __restrict__ Wp1, const float* __restrict__ bp1,
                    const float* __restrict__ Wp2, const float* __restrict__ bp2,
                    float* __restrict__ o1, float* __restrict__ o2)
{
    const int r = blockIdx.x, n = blockIdx.y * 128 + threadIdx.x;
    __shared__ float w1[GG][EE], w2[GG][EE], b1s[GG], b2s[GG];
    for (int i = threadIdx.x; i < GG*EE; i += 128) { w1[i>>6][i&63] = Wp1[i]; w2[i>>6][i&63] = Wp2[i]; }
    if (threadIdx.x < GG) { b1s[threadIdx.x] = bp1[threadIdx.x]; b2s[threadIdx.x] = bp2[threadIdx.x]; }
    __syncthreads();
    float4 pr[EE/4];
    const float4* src = (const float4*)(pe + (((long)r * RR) + n) * EE);
#pragma unroll
    for (int i = 0; i < EE/4; i++) pr[i] = src[i];
#pragma unroll 1
    for (int g = 0; g < GG; ++g) {
        const float4* a = (const float4*)w1[g];
        const float4* b = (const float4*)w2[g];
        float s1 = 0.f, s2 = 0.f;
#pragma unroll
        for (int i = 0; i < EE/4; i++) {
            float4 p = pr[i], xx = a[i], yy = b[i];
            s1 += p.x*xx.x + p.y*xx.y + p.z*xx.z + p.w*xx.w;
            s2 += p.x*yy.x + p.y*yy.y + p.z*yy.z + p.w*yy.w;
        }
        long o = ((long)r * GG + g) * RR + n;
        o1[o] = logf(fmaxf(s1 + b1s[g], 1e-6f));
        o2[o] = logf(fmaxf(s2 + b2s[g], 1e-6f));
    }
}

// ---------------- fp32 -> bf16 hi/lo split ----------------
__global__ __launch_bounds__(256)
void splitk(const float* __restrict__ in, __nv_bfloat16* __restrict__ hi,
            __nv_bfloat16* __restrict__ lo, long n4)
{
    for (long i = (long)blockIdx.x * 256 + threadIdx.x; i < n4; i += (long)gridDim.x * 256) {
        float4 v = ((const float4*)in)[i];
        __nv_bfloat16 a = __float2bfloat16(v.x), b = __float2bfloat16(v.y);
        __nv_bfloat16 c = __float2bfloat16(v.z), d = __float2bfloat16(v.w);
        ((__nv_bfloat162*)hi)[2*i]   = __halves2bfloat162(a, b);
        ((__nv_bfloat162*)hi)[2*i+1] = __halves2bfloat162(c, d);
        ((__nv_bfloat162*)lo)[2*i]   = __halves2bfloat162(
            __float2bfloat16(v.x - __bfloat162float(a)), __float2bfloat16(v.y - __bfloat162float(b)));
        ((__nv_bfloat162*)lo)[2*i+1] = __halves2bfloat162(
            __float2bfloat16(v.z - __bfloat162float(c)), __float2bfloat16(v.w - __bfloat162float(d)));
    }
}

// fc1 split-K reduce: h = p0 + p1 + bias; also emit hh/hl
__global__ __launch_bounds__(256)
void reduce_fc1(const float* __restrict__ p, const float* __restrict__ bias,
                float* __restrict__ h, __nv_bfloat16* __restrict__ hh,
                __nv_bfloat16* __restrict__ hl)
{
    long i = (long)blockIdx.x * 256 + threadIdx.x;        // float4 index over RR*DD/4
    float4 a = ((const float4*)p)[i];
    float4 b = ((const float4*)p)[i + (long)RR*DD/4];
    float4 bb = ((const float4*)bias)[i & (DD/4 - 1)];
    float4 v = make_float4(a.x+b.x+bb.x, a.y+b.y+bb.y, a.z+b.z+bb.z, a.w+b.w+bb.w);
    ((float4*)h)[i] = v;
    st_hilo(hh, hl, i*4,     v.x, v.y);
    st_hilo(hh, hl, i*4 + 2, v.z, v.w);
}

// virtual concat [h | a | h+a] -> bf16 hi/lo
__global__ __launch_bounds__(256)
void catsplit(const float* __restrict__ h, const float* __restrict__ a,
              __nv_bfloat16* __restrict__ hi, __nv_bfloat16* __restrict__ lo)
{
    long i = (long)blockIdx.x * 256 + threadIdx.x;
    long e = i * 4;
    int r = (int)(e / (3*DD)), c = (int)(e % (3*DD));
    float4 v;
    if (c < DD) v = *(const float4*)(h + (long)r*DD + c);
    else if (c < 2*DD) v = *(const float4*)(a + (long)r*DD + c - DD);
    else {
        float4 x = *(const float4*)(h + (long)r*DD + c - 2*DD);
        float4 y = *(const float4*)(a + (long)r*DD + c - 2*DD);
        v = make_float4(x.x+y.x, x.y+y.y, x.z+y.z, x.w+y.w);
    }
    __nv_bfloat16 a0 = __float2bfloat16(v.x), b0 = __float2bfloat16(v.y);
    __nv_bfloat16 c0 = __float2bfloat16(v.z), d0 = __float2bfloat16(v.w);
    ((__nv_bfloat162*)hi)[2*i]   = __halves2bfloat162(a0, b0);
    ((__nv_bfloat162*)hi)[2*i+1] = __halves2bfloat162(c0, d0);
    ((__nv_bfloat162*)lo)[2*i]   = __halves2bfloat162(
        __float2bfloat16(v.x - __bfloat162float(a0)), __float2bfloat16(v.y - __bfloat162float(b0)));
    ((__nv_bfloat162*)lo)[2*i+1] = __halves2bfloat162(
        __float2bfloat16(v.z - __bfloat162float(c0)), __float2bfloat16(v.w - __bfloat162float(d0)));
}

// ---------------- softmax: fp32 in, bf16 hi/lo out ----------------
__global__ __launch_bounds__(256)
void softmax_kernel(const float* __restrict__ S, const float* __restrict__ bias,
                    __nv_bfloat16* __restrict__ Ph, __nv_bfloat16* __restrict__ Pl)
{
    const int i = blockIdx.x, g = blockIdx.y, tid = threadIdx.x;
    const long base = ((long)g * RR + i) * RR;
    float4 rv = ((const float4*)(S + base))[tid];
    float4 bv = ((const float4*)(bias + ((long)i * GG + g) * RR))[tid];
    float w[4] = { rv.x + bv.x, rv.y + bv.y, rv.z + bv.z, rv.w + bv.w };
    float mx = fmaxf(fmaxf(w[0], w[1]), fmaxf(w[2], w[3]));
    __shared__ float red[8];
#pragma unroll
    for (int o = 16; o > 0; o >>= 1) mx = fmaxf(mx, __shfl_xor_sync(~0u, mx, o));
    if ((tid & 31) == 0) red[tid >> 5] = mx;
    __syncthreads();
    float m2 = red[0];
#pragma unroll
    for (int k = 1; k < 8; k++) m2 = fmaxf(m2, red[k]);
    float sum = 0.f;
#pragma unroll
    for (int j = 0; j < 4; j++) { w[j] = __expf(w[j] - m2); sum += w[j]; }
#pragma unroll
    for (int o = 16; o > 0; o >>= 1) sum += __shfl_xor_sync(~0u, sum, o);
    __syncthreads();
    if ((tid & 31) == 0) red[tid >> 5] = sum;
    __syncthreads();
    float s2 = 0.f;
#pragma unroll
    for (int k = 0; k < 8; k++) s2 += red[k];
    float inv = 1.f / s2;
    long o = base + tid*4;
    st_hilo(Ph, Pl, o,     w[0]*inv, w[1]*inv);
    st_hilo(Ph, Pl, o + 2, w[2]*inv, w[3]*inv);
}

// ---------------- mma.sync split-precision GEMM ----------------
// 2-stage cp.async (98 KB smem -> 2 CTAs/SM); paired ldsm4 for B.
#define ATB  16384              // 128 x 64 bf16
#define BTB  8192               // 64 x 64 bf16
#define MBUF (2*ATB + 2*BTB)    // 49152: [Ah|Al|Bh|Bl]
#define MSMEM (2*MBUF)          // 98304, 2 stages

template<bool HASC, bool HASB>
__global__ void __launch_bounds__(256, 2)
mmag(const __nv_bfloat16* __restrict__ Ah, const __nv_bfloat16* __restrict__ Al, int lda, long aZ,
     const __nv_bfloat16* __restrict__ Bh, const __nv_bfloat16* __restrict__ Bl, int ldb, long bZ,
     float* __restrict__ C, __nv_bfloat16* __restrict__ Chi, __nv_bfloat16* __restrict__ Clo,
     int ldc, long cZ,
     int K, float alpha, const float* __restrict__ bias, long biasZ, int relu)
{
    extern __shared__ __align__(1024) char smem[];
    const uint32_t sb = smem_u32(smem);
    const int tid = threadIdx.x, lane = tid & 31, wid = tid >> 5;
    const int warp_m = wid & 3, warp_n = wid >> 2;       // 4 x 2
    const int m0 = blockIdx.y * 128, n0 = blockIdx.x * 64;
    const long z = blockIdx.z;
    Ah += z * aZ; Al += z * aZ; Bh += z * bZ; Bl += z * bZ;
    const long coff = z * cZ;
    const float* bp = bias ? bias + z * biasZ : nullptr;

    float acc[2][4][4];
#pragma unroll
    for (int i = 0; i < 2; i++)
#pragma unroll
        for (int j = 0; j < 4; j++)
#pragma unroll
            for (int q = 0; q < 4; q++) acc[i][j][q] = 0.f;

    const int nc = K >> 6;

    auto load_chunk = [&](int c, int buf) {
        const int kk = c << 6;
        const uint32_t base = sb + buf * MBUF;
#pragma unroll
        for (int it = 0; it < 4; it++) {
            int idx = tid + it * 256;
            int row = idx >> 3, g = idx & 7;
            uint32_t d = base + SWZ(row*128 + g*16);
            long off = (long)(m0 + row) * lda + kk + g*8;
            cpasync16(d,       Ah + off);
            cpasync16(d + ATB, Al + off);
        }
#pragma unroll
        for (int it = 0; it < 2; it++) {
            int idx = tid + it * 256;
            int row = idx >> 3, g = idx & 7;
            uint32_t d = base + 2*ATB + SWZ(row*128 + g*16);
            long off = (long)(n0 + row) * ldb + kk + g*8;
            cpasync16(d,       Bh + off);
            cpasync16(d + BTB, Bl + off);
        }
        asm volatile("cp.async.commit_group;");
    };

    load_chunk(0, 0);

    const int rA  = warp_m*32 + (lane & 7) + ((lane >> 3) & 1)*8;   // + i*16
    const int cAb = ((lane >> 4) & 1) * 16;                          // + ks*32
    // B paired ldsm4: lanes 0-15 -> block 2*j2 (k-lo/k-hi), lanes 16-31 -> block 2*j2+1
    const int rB4 = warp_n*32 + ((lane >> 4) & 1)*8 + (lane & 7);    // + j2*16
    const int cBb = ((lane >> 3) & 1) * 16;                          // + ks*32

    for (int c = 0; c < nc; c++) {
        const int buf = c & 1;
        if (c + 1 < nc) load_chunk(c + 1, buf ^ 1);
        if (c + 1 < nc) asm volatile("cp.async.wait_group 1;");
        else            asm volatile("cp.async.wait_group 0;");
        __syncthreads();

        const uint32_t ab  = sb + buf * MBUF;
        const uint32_t alb = ab + ATB, bhb = ab + 2*ATB, blb = ab + 2*ATB + BTB;
#pragma unroll
        for (int ks = 0; ks < 4; ks++) {
            uint32_t ah[2][4], al[2][4], bh[4][2], bl[4][2];
#pragma unroll
            for (int i = 0; i < 2; i++) {
                uint32_t o = SWZ((rA + i*16)*128 + ks*32 + cAb);
                ldsm4(ah[i], ab + o);
                ldsm4(al[i], alb + o);
            }
#pragma unroll
            for (int j2 = 0; j2 < 2; j2++) {
                uint32_t o = SWZ((rB4 + j2*16)*128 + ks*32 + cBb);
                ldsm4(&bh[2*j2][0], bhb + o);
                ldsm4(&bl[2*j2][0], blb + o);
            }
#pragma unroll
            for (int i = 0; i < 2; i++)
#pragma unroll
                for (int j = 0; j < 4; j++) {
                    mma16816(acc[i][j], ah[i], bh[j]);
                    mma16816(acc[i][j], al[i], bh[j]);
                    mma16816(acc[i][j], ah[i], bl[j]);
                }
        }
        __syncthreads();
    }

#pragma unroll
    for (int i = 0; i < 2; i++) {
        int m = m0 + warp_m*32 + i*16 + (lane >> 2);
#pragma unroll
        for (int j = 0; j < 4; j++) {
            int n = n0 + warp_n*32 + j*8 + (lane & 3)*2;
            float b0v = bp ? bp[n] : 0.f, b1v = bp ? bp[n+1] : 0.f;
            float r0 = acc[i][j][0]*alpha + b0v, r1 = acc[i][j][1]*alpha + b1v;
            float r2 = acc[i][j][2]*alpha + b0v, r3 = acc[i][j][3]*alpha + b1v;
            if (relu) { r0=fmaxf(r0,0.f); r1=fmaxf(r1,0.f); r2=fmaxf(r2,0.f); r3=fmaxf(r3,0.f); }
            long o0 = coff + (long)m*ldc + n, o1 = coff + (long)(m+8)*ldc + n;
            if (HASC) {
                *(float2*)(C + o0) = make_float2(r0, r1);
                *(float2*)(C + o1) = make_float2(r2, r3);
            }
            if (HASB) {
                st_hilo(Chi, Clo, o0, r0, r1);
                st_hilo(Chi, Clo, o1, r2, r3);
            }
        }
    }
}

// ---------------- host orchestration ----------------
static __nv_bfloat16 *xh,*xl,*w1h,*w1l,*w2h,*w2l;
static __nv_bfloat16 *wq1h,*wq1l,*wk1h,*wk1l,*wo1h,*wo1l,*wa1h,*wa1l;
static __nv_bfloat16 *wq2h,*wq2l,*wk2h,*wk2l,*wo2h,*wo2l,*wa2h,*wa2l;
static __nv_bfloat16 *hh,*hl,*h2h,*h2l,*qh,*ql,*kh,*kl,*vth,*vtl,*cch,*ccl,*Ph,*Pl;
static float *h,*att,*S,*B1,*B2,*pP;

static cudaStream_t sA, sB;
static cudaEvent_t EV[12];
static bool g_init = false;

static inline void do_split(const float* s, __nv_bfloat16* hi, __nv_bfloat16* lo, long n,
                            cudaStream_t st) {
    long n4 = n >> 2;
    int grid = (int)((n4 + 255) / 256); if (grid > 4096) grid = 4096;
    splitk<<<grid, 256, 0, st>>>(s, hi, lo, n4);
}

struct BlkW {
    __nv_bfloat16 *qh,*ql,*kh,*kl,*oh,*ol,*ah,*al;
    const float *bq,*bk,*bo,*ba;
    const float* biasLog;
};

static void relation_block(const BlkW& W, float* outC, __nv_bfloat16* outHi, __nv_bfloat16* outLo,
                           cudaEvent_t eH, cudaEvent_t eK, cudaEvent_t eV)
{
    cudaEventRecord(eH, 0);
    cudaStreamWaitEvent(sA, eH, 0);
    cudaStreamWaitEvent(sB, eH, 0);
    mmag<false,true><<<dim3(16,8,1),256,MSMEM,0>>>(hh,hl,DD,0, W.qh,W.ql,DD,0,
                                       nullptr,qh,ql, DD,0, DD,1.f, W.bq,0,0);
    mmag<false,true><<<dim3(16,8,1),256,MSMEM,sA>>>(hh,hl,DD,0, W.kh,W.kl,DD,0,
                                        nullptr,kh,kl, DD,0, DD,1.f, W.bk,0,0);
    cudaEventRecord(eK, sA);
    mmag<false,true><<<dim3(16,8,1),256,MSMEM,sB>>>(W.oh,W.ol,DD,0, hh,hl,DD,0,
                                        nullptr,vth,vtl, RR,0, DD,1.f, nullptr,0,0);
    cudaEventRecord(eV, sB);
    // S[g] = 0.125 * Q_g K_g^T  (fp32)
    cudaStreamWaitEvent(0, eK, 0);
    mmag<true,false><<<dim3(16,8,GG),256,MSMEM,0>>>(qh,ql,DD,DGB, kh,kl,DD,DGB,
                                        S,nullptr,nullptr, RR,(long)RR*RR, DGB,0.125f, nullptr,0,0);
    cudaStreamWaitEvent(0, EV[1], 0);
    softmax_kernel<<<dim3(RR,GG),256,0,0>>>(S, W.biasLog, Ph, Pl);
    cudaStreamWaitEvent(0, eV, 0);
    mmag<true,false><<<dim3(1,8,GG),256,MSMEM,0>>>(Ph,Pl,RR,(long)RR*RR, vth,vtl,RR,(long)DGB*RR,
                                       att,nullptr,nullptr, DD,DGB, RR,1.f, W.bo,DGB,0);
    catsplit<<<(RR*3*DD/4)/256, 256, 0, 0>>>(h, att, cch, ccl);
    if (outC)
        mmag<true,false><<<dim3(16,8,1),256,MSMEM,0>>>(cch,ccl,3*DD,0, W.ah,W.al,3*DD,0,
                                       outC,nullptr,nullptr, DD,0, 3*DD,1.f, W.ba,0,1);
    else
        mmag<false,true><<<dim3(16,8,1),256,MSMEM,0>>>(cch,ccl,3*DD,0, W.ah,W.al,3*DD,0,
                                       nullptr,outHi,outLo, DD,0, 3*DD,1.f, W.ba,0,1);
}

extern "C" void kernel_launch(void* const* d_in, const int* in_sizes, int n_in,
                              void* d_out, int out_size)
{
    const float* x    = (const float*)d_in[0];
    const float* pe   = (const float*)d_in[1];
    const float* Wfc1 = (const float*)d_in[2];  const float* bfc1 = (const float*)d_in[3];
    const float* Wfc2 = (const float*)d_in[4];  const float* bfc2 = (const float*)d_in[5];
    const float* Wp1  = (const float*)d_in[6];  const float* bp1  = (const float*)d_in[7];
    const float* Wq1  = (const float*)d_in[8];  const float* bq1  = (const float*)d_in[9];
    const float* Wk1  = (const float*)d_in[10]; const float* bk1  = (const float*)d_in[11];
    const float* Wo1  = (const float*)d_in[12]; const float* bo1  = (const float*)d_in[13];
    const float* Wa1  = (const float*)d_in[14]; const float* ba1  = (const float*)d_in[15];
    const float* Wp2  = (const float*)d_in[16]; const float* bp2  = (const float*)d_in[17];
    const float* Wq2  = (const float*)d_in[18]; const float* bq2  = (const float*)d_in[19];
    const float* Wk2  = (const float*)d_in[20]; const float* bk2  = (const float*)d_in[21];
    const float* Wo2  = (const float*)d_in[22]; const float* bo2  = (const float*)d_in[23];
    const float* Wa2  = (const float*)d_in[24]; const float* ba2  = (const float*)d_in[25];
    float* out = (float*)d_out;

    if (!g_init) {
        cudaStreamCreateWithFlags(&sA, cudaStreamNonBlocking);
        cudaStreamCreateWithFlags(&sB, cudaStreamNonBlocking);
        for (int i = 0; i < 12; i++) cudaEventCreateWithFlags(&EV[i], cudaEventDisableTiming);
        g_init = true;
    }

    cudaFuncSetAttribute(mmag<true,true>,   cudaFuncAttributeMaxDynamicSharedMemorySize, MSMEM);
    cudaFuncSetAttribute(mmag<false,true>,  cudaFuncAttributeMaxDynamicSharedMemorySize, MSMEM);
    cudaFuncSetAttribute(mmag<true,false>,  cudaFuncAttributeMaxDynamicSharedMemorySize, MSMEM);

    cudaGetSymbolAddress((void**)&h, g_h);     cudaGetSymbolAddress((void**)&att, g_att);
    cudaGetSymbolAddress((void**)&S, g_S);     cudaGetSymbolAddress((void**)&pP, g_p);
    cudaGetSymbolAddress((void**)&B1, g_B1);   cudaGetSymbolAddress((void**)&B2, g_B2);
    cudaGetSymbolAddress((void**)&xh, g_xh);   cudaGetSymbolAddress((void**)&xl, g_xl);
    cudaGetSymbolAddress((void**)&w1h, g_w1h); cudaGetSymbolAddress((void**)&w1l, g_w1l);
    cudaGetSymbolAddress((void**)&w2h, g_w2h); cudaGetSymbolAddress((void**)&w2l, g_w2l);
    cudaGetSymbolAddress((void**)&wq1h, g_wq1h); cudaGetSymbolAddress((void**)&wq1l, g_wq1l);
    cudaGetSymbolAddress((void**)&wk1h, g_wk1h); cudaGetSymbolAddress((void**)&wk1l, g_wk1l);
    cudaGetSymbolAddress((void**)&wo1h, g_wo1h); cudaGetSymbolAddress((void**)&wo1l, g_wo1l);
    cudaGetSymbolAddress((void**)&wa1h, g_wa1h); cudaGetSymbolAddress((void**)&wa1l, g_wa1l);
    cudaGetSymbolAddress((void**)&wq2h, g_wq2h); cudaGetSymbolAddress((void**)&wq2l, g_wq2l);
    cudaGetSymbolAddress((void**)&wk2h, g_wk2h); cudaGetSymbolAddress((void**)&wk2l, g_wk2l);
    cudaGetSymbolAddress((void**)&wo2h, g_wo2h); cudaGetSymbolAddress((void**)&wo2l, g_wo2l);
    cudaGetSymbolAddress((void**)&wa2h, g_wa2h); cudaGetSymbolAddress((void**)&wa2l, g_wa2l);
    cudaGetSymbolAddress((void**)&hh, g_hh);   cudaGetSymbolAddress((void**)&hl, g_hl);
    cudaGetSymbolAddress((void**)&h2h, g_h2h); cudaGetSymbolAddress((void**)&h2l, g_h2l);
    cudaGetSymbolAddress((void**)&qh, g_qh);   cudaGetSymbolAddress((void**)&ql, g_ql);
    cudaGetSymbolAddress((void**)&kh, g_kh);   cudaGetSymbolAddress((void**)&kl, g_kl);
    cudaGetSymbolAddress((void**)&vth, g_vth); cudaGetSymbolAddress((void**)&vtl, g_vtl);
    cudaGetSymbolAddress((void**)&cch, g_cch); cudaGetSymbolAddress((void**)&ccl, g_ccl);
    cudaGetSymbolAddress((void**)&Ph, g_Ph);   cudaGetSymbolAddress((void**)&Pl, g_Pl);

    // ---- fork ----
    cudaEventRecord(EV[0], 0);
    cudaStreamWaitEvent(sA, EV[0], 0);
    cudaStreamWaitEvent(sB, EV[0], 0);

    // sA: position bias (memory-bound, overlaps fc1)
    posbias_kernel<<<dim3(RR, RR/128), 128, 0, sA>>>(pe, Wp1, bp1, Wp2, bp2, B1, B2);
    cudaEventRecord(EV[1], sA);

    // sB: splits — x+Wfc1 first (fc1 gate), then remaining weights
    do_split(x, xh, xl, (long)RR*KFC1, sB);
    do_split(Wfc1, w1h, w1l, (long)DD*KFC1, sB);
    cudaEventRecord(EV[2], sB);
    do_split(Wq1, wq1h, wq1l, (long)DD*DD, sB);
    do_split(Wk1, wk1h, wk1l, (long)DD*DD, sB);
    do_split(Wo1, wo1h, wo1l, (long)DD*DD, sB);
    do_split(Wa1, wa1h, wa1l, (long)DD*3*DD, sB);
    do_split(Wfc2, w2h, w2l, (long)DD*DD, sB);
    do_split(Wq2, wq2h, wq2l, (long)DD*DD, sB);
    do_split(Wk2, wk2h, wk2l, (long)DD*DD, sB);
    do_split(Wo2, wo2h, wo2l, (long)DD*DD, sB);
    do_split(Wa2, wa2h, wa2l, (long)DD*3*DD, sB);
    cudaEventRecord(EV[3], sB);

    // stream 0: fc1 split-K=2 after x/Wfc1 splits, then reduce + split
    cudaStreamWaitEvent(0, EV[2], 0);
    mmag<true,false><<<dim3(16,8,2),256,MSMEM,0>>>(xh,xl,KFC1,KHALF, w1h,w1l,KFC1,KHALF,
                                       pP,nullptr,nullptr, DD,(long)RR*DD, KHALF,1.f, nullptr,0,0);
    reduce_fc1<<<RR*DD/4/256, 256, 0, 0>>>(pP, bfc1, h, hh, hl);

    cudaStreamWaitEvent(0, EV[3], 0);
    cudaStreamWaitEvent(sA, EV[3], 0);
    cudaStreamWaitEvent(sB, EV[3], 0);

    // relation block 1 -> h2 (bf16 only)
    BlkW W1b = { wq1h,wq1l, wk1h,wk1l, wo1h,wo1l, wa1h,wa1l, bq1,bk1,bo1,ba1, B1 };
    relation_block(W1b, nullptr, h2h, h2l, EV[4], EV[5], EV[6]);

    // fc2: h = h2 @ Wfc2^T + bfc2
    mmag<true,true><<<dim3(16,8,1),256,MSMEM,0>>>(h2h,h2l,DD,0, w2h,w2l,DD,0,
                                       h,hh,hl, DD,0, DD,1.f, bfc2,0,0);

    // relation block 2 -> out (fp32)
    BlkW W2b = { wq2h,wq2l, wk2h,wk2l, wo2h,wo2l, wa2h,wa2l, bq2,bk2,bo2,ba2, B2 };
    relation_block(W2b, out, nullptr, nullptr, EV[7], EV[8], EV[9]);
}

// round 16
// speedup vs baseline: 1.9287x; 1.0023x over previous
#include <cuda_runtime.h>
#include <cuda_bf16.h>
#include <math.h>
#include <stdint.h>

#define RR   1024
#define GG   16
#define DD   1024
#define DGB  64
#define EE   64
#define KFC1 12544
#define KHALF 6272

#define SWZ(o) ((o) ^ (((o) >> 3) & 0x70))

__device__ __forceinline__ uint32_t smem_u32(const void* p) {
    uint32_t a;
    asm("{ .reg .u64 t; cvta.to.shared.u64 t, %1; cvt.u32.u64 %0, t; }" : "=r"(a) : "l"(p));
    return a;
}
__device__ __forceinline__ void cpasync16(uint32_t dst, const void* src) {
    asm volatile("cp.async.cg.shared.global [%0], [%1], 16;" :: "r"(dst), "l"(src));
}
__device__ __forceinline__ void ldsm4(uint32_t* r, uint32_t a) {
    asm volatile("ldmatrix.sync.aligned.m8n8.x4.shared.b16 {%0,%1,%2,%3}, [%4];"
                 : "=r"(r[0]), "=r"(r[1]), "=r"(r[2]), "=r"(r[3]) : "r"(a));
}
__device__ __forceinline__ void mma16816(float* c, const uint32_t* a, const uint32_t* b) {
    asm volatile("mma.sync.aligned.m16n8k16.row.col.f32.bf16.bf16.f32 "
                 "{%0,%1,%2,%3}, {%4,%5,%6,%7}, {%8,%9}, {%0,%1,%2,%3};"
                 : "+f"(c[0]), "+f"(c[1]), "+f"(c[2]), "+f"(c[3])
                 : "r"(a[0]), "r"(a[1]), "r"(a[2]), "r"(a[3]), "r"(b[0]), "r"(b[1]));
}
__device__ __forceinline__ void st_hilo(__nv_bfloat16* Chi, __nv_bfloat16* Clo, long off,
                                        float r0, float r1) {
    __nv_bfloat16 h0 = __float2bfloat16(r0), h1 = __float2bfloat16(r1);
    *(__nv_bfloat162*)(Chi + off) = __halves2bfloat162(h0, h1);
    *(__nv_bfloat162*)(Clo + off) = __halves2bfloat162(
        __float2bfloat16(r0 - __bfloat162float(h0)),
        __float2bfloat16(r1 - __bfloat162float(h1)));
}

// ---------------- scratch ----------------
__device__ float g_h[RR*DD], g_att[RR*DD];
__device__ float g_p[2*RR*DD];                       // split-K partials (shared scratch)
__device__ float g_S[(long)GG*RR*RR];
__device__ float g_B1[(long)RR*GG*RR], g_B2[(long)RR*GG*RR];
__device__ __nv_bfloat16 g_xh[RR*KFC1], g_xl[RR*KFC1];
__device__ __nv_bfloat16 g_w1h[DD*KFC1], g_w1l[DD*KFC1];
__device__ __nv_bfloat16 g_w2h[DD*DD],   g_w2l[DD*DD];
__device__ __nv_bfloat16 g_wq1h[DD*DD], g_wq1l[DD*DD], g_wk1h[DD*DD], g_wk1l[DD*DD];
__device__ __nv_bfloat16 g_wo1h[DD*DD], g_wo1l[DD*DD], g_wa1h[DD*3*DD], g_wa1l[DD*3*DD];
__device__ __nv_bfloat16 g_wq2h[DD*DD], g_wq2l[DD*DD], g_wk2h[DD*DD], g_wk2l[DD*DD];
__device__ __nv_bfloat16 g_wo2h[DD*DD], g_wo2l[DD*DD], g_wa2h[DD*3*DD], g_wa2l[DD*3*DD];
__device__ __nv_bfloat16 g_hh[RR*DD],  g_hl[RR*DD];
__device__ __nv_bfloat16 g_h2h[RR*DD], g_h2l[RR*DD];
__device__ __nv_bfloat16 g_qh[RR*DD],  g_ql[RR*DD];
__device__ __nv_bfloat16 g_kh[RR*DD],  g_kl[RR*DD];
__device__ __nv_bfloat16 g_vth[DD*RR], g_vtl[DD*RR];
__device__ __nv_bfloat16 g_cch[RR*3*DD], g_ccl[RR*3*DD];
__device__ __nv_bfloat16 g_Ph[(long)GG*RR*RR], g_Pl[(long)GG*RR*RR];

// ---------------- position bias ----------------
__global__ __launch_bounds__(128)
void posbias_kernel(const float* __restrict__ pe,
                    const float* __restrict__ Wp1, const float* __restrict__ bp1,
                    const float* __restrict__ Wp2, const float* __restrict__ bp2,
                    float* __restrict__ o1, float* __restrict__ o2)
{
    const int r = blockIdx.x, n = blockIdx.y * 128 + threadIdx.x;
    __shared__ float w1[GG][EE], w2[GG][EE], b1s[GG], b2s[GG];
    for (int i = threadIdx.x; i < GG*EE; i += 128) { w1[i>>6][i&63] = Wp1[i]; w2[i>>6][i&63] = Wp2[i]; }
    if (threadIdx.x < GG) { b1s[threadIdx.x] = bp1[threadIdx.x]; b2s[threadIdx.x] = bp2[threadIdx.x]; }
    __syncthreads();
    float4 pr[EE/4];
    const float4* src = (const float4*)(pe + (((long)r * RR) + n) * EE);
#pragma unroll
    for (int i = 0; i < EE/4; i++) pr[i] = src[i];
#pragma unroll 1
    for (int g = 0; g < GG; ++g) {
        const float4* a = (const float4*)w1[g];
        const float4* b = (const float4*)w2[g];
        float s1 = 0.f, s2 = 0.f;
#pragma unroll
        for (int i = 0; i < EE/4; i++) {
            float4 p = pr[i], xx = a[i], yy = b[i];
            s1 += p.x*xx.x + p.y*xx.y + p.z*xx.z + p.w*xx.w;
            s2 += p.x*yy.x + p.y*yy.y + p.z*yy.z + p.w*yy.w;
        }
        long o = ((long)r * GG + g) * RR + n;
        o1[o] = logf(fmaxf(s1 + b1s[g], 1e-6f));
        o2[o] = logf(fmaxf(s2 + b2s[g], 1e-6f));
    }
}

// ---------------- fp32 -> bf16 hi/lo split ----------------
__global__ __launch_bounds__(256)
void splitk(const float* __restrict__ in, __nv_bfloat16* __restrict__ hi,
            __nv_bfloat16* __restrict__ lo, long n4)
{
    for (long i = (long)blockIdx.x * 256 + threadIdx.x; i < n4; i += (long)gridDim.x * 256) {
        float4 v = ((const float4*)in)[i];
        __nv_bfloat16 a = __float2bfloat16(v.x), b = __float2bfloat16(v.y);
        __nv_bfloat16 c = __float2bfloat16(v.z), d = __float2bfloat16(v.w);
        ((__nv_bfloat162*)hi)[2*i]   = __halves2bfloat162(a, b);
        ((__nv_bfloat162*)hi)[2*i+1] = __halves2bfloat162(c, d);
        ((__nv_bfloat162*)lo)[2*i]   = __halves2bfloat162(
            __float2bfloat16(v.x - __bfloat162float(a)), __float2bfloat16(v.y - __bfloat162float(b)));
        ((__nv_bfloat162*)lo)[2*i+1] = __halves2bfloat162(
            __float2bfloat16(v.z - __bfloat162float(c)), __float2bfloat16(v.w - __bfloat162float(d)));
    }
}

// split-K reduce: v = p0 + p1 + bias, opt relu; outputs fp32 and/or bf16 hi/lo
template<bool HASF, bool HASB, bool RELU>
__global__ __launch_bounds__(256)
void reduce2(const float* __restrict__ p, const float* __restrict__ bias,
             float* __restrict__ f, __nv_bfloat16* __restrict__ hh,
             __nv_bfloat16* __restrict__ hl)
{
    long i = (long)blockIdx.x * 256 + threadIdx.x;        // float4 index over RR*DD/4
    float4 a = ((const float4*)p)[i];
    float4 b = ((const float4*)p)[i + (long)RR*DD/4];
    float4 bb = ((const float4*)bias)[i & (DD/4 - 1)];
    float4 v = make_float4(a.x+b.x+bb.x, a.y+b.y+bb.y, a.z+b.z+bb.z, a.w+b.w+bb.w);
    if (RELU) { v.x = fmaxf(v.x, 0.f); v.y = fmaxf(v.y, 0.f); v.z = fmaxf(v.z, 0.f); v.w = fmaxf(v.w, 0.f); }
    if (HASF) ((float4*)f)[i] = v;
    if (HASB) {
        st_hilo(hh, hl, i*4,     v.x, v.y);
        st_hilo(hh, hl, i*4 + 2, v.z, v.w);
    }
}

// virtual concat [h | a | h+a] -> bf16 hi/lo
__global__ __launch_bounds__(256)
void catsplit(const float* __restrict__ h, const float* __restrict__ a,
              __nv_bfloat16* __restrict__ hi, __nv_bfloat16* __restrict__ lo)
{
    long i = (long)blockIdx.x * 256 + threadIdx.x;
    long e = i * 4;
    int r = (int)(e / (3*DD)), c = (int)(e % (3*DD));
    float4 v;
    if (c < DD) v = *(const float4*)(h + (long)r*DD + c);
    else if (c < 2*DD) v = *(const float4*)(a + (long)r*DD + c - DD);
    else {
        float4 x = *(const float4*)(h + (long)r*DD + c - 2*DD);
        float4 y = *(const float4*)(a + (long)r*DD + c - 2*DD);
        v = make_float4(x.x+y.x, x.y+y.y, x.z+y.z, x.w+y.w);
    }
    __nv_bfloat16 a0 = __float2bfloat16(v.x), b0 = __float2bfloat16(v.y);
    __nv_bfloat16 c0 = __float2bfloat16(v.z), d0 = __float2bfloat16(v.w);
    ((__nv_bfloat162*)hi)[2*i]   = __halves2bfloat162(a0, b0);
    ((__nv_bfloat162*)hi)[2*i+1] = __halves2bfloat162(c0, d0);
    ((__nv_bfloat162*)lo)[2*i]   = __halves2bfloat162(
        __float2bfloat16(v.x - __bfloat162float(a0)), __float2bfloat16(v.y - __bfloat162float(b0)));
    ((__nv_bfloat162*)lo)[2*i+1] = __halves2bfloat162(
        __float2bfloat16(v.z - __bfloat162float(c0)), __float2bfloat16(v.w - __bfloat162float(d0)));
}

// ---------------- softmax: fp32 in, bf16 hi/lo out ----------------
__global__ __launch_bounds__(256)
void softmax_kernel(const float* __restrict__ S, const float* __restrict__ bias,
                    __nv_bfloat16* __restrict__ Ph, __nv_bfloat16* __restrict__ Pl)
{
    const int i = blockIdx.x, g = blockIdx.y, tid = threadIdx.x;
    const long base = ((long)g * RR + i) * RR;
    float4 rv = ((const float4*)(S + base))[tid];
    float4 bv = ((const float4*)(bias + ((long)i * GG + g) * RR))[tid];
    float w[4] = { rv.x + bv.x, rv.y + bv.y, rv.z + bv.z, rv.w + bv.w };
    float mx = fmaxf(fmaxf(w[0], w[1]), fmaxf(w[2], w[3]));
    __shared__ float red[8];
#pragma unroll
    for (int o = 16; o > 0; o >>= 1) mx = fmaxf(mx, __shfl_xor_sync(~0u, mx, o));
    if ((tid & 31) == 0) red[tid >> 5] = mx;
    __syncthreads();
    float m2 = red[0];
#pragma unroll
    for (int k = 1; k < 8; k++) m2 = fmaxf(m2, red[k]);
    float sum = 0.f;
#pragma unroll
    for (int j = 0; j < 4; j++) { w[j] = __expf(w[j] - m2); sum += w[j]; }
#pragma unroll
    for (int o = 16; o > 0; o >>= 1) sum += __shfl_xor_sync(~0u, sum, o);
    __syncthreads();
    if ((tid & 31) == 0) red[tid >> 5] = sum;
    __syncthreads();
    float s2 = 0.f;
#pragma unroll
    for (int k = 0; k < 8; k++) s2 += red[k];
    float inv = 1.f / s2;
    long o = base + tid*4;
    st_hilo(Ph, Pl, o,     w[0]*inv, w[1]*inv);
    st_hilo(Ph, Pl, o + 2, w[2]*inv, w[3]*inv);
}

// ---------------- mma.sync split-precision GEMM ----------------
// 2-stage cp.async (98 KB smem -> 2 CTAs/SM); paired ldsm4 for B.
#define ATB  16384              // 128 x 64 bf16
#define BTB  8192               // 64 x 64 bf16
#define MBUF (2*ATB + 2*BTB)    // 49152: [Ah|Al|Bh|Bl]
#define MSMEM (2*MBUF)          // 98304, 2 stages

template<bool HASC, bool HASB>
__global__ void __launch_bounds__(256, 2)
mmag(const __nv_bfloat16* __restrict__ Ah, const __nv_bfloat16* __restrict__ Al, int lda, long aZ,
     const __nv_bfloat16* __restrict__ Bh, const __nv_bfloat16* __restrict__ Bl, int ldb, long bZ,
     float* __restrict__ C, __nv_bfloat16* __restrict__ Chi, __nv_bfloat16* __restrict__ Clo,
     int ldc, long cZ,
     int K, float alpha, const float* __restrict__ bias, long biasZ, int relu)
{
    extern __shared__ __align__(1024) char smem[];
    const uint32_t sb = smem_u32(smem);
    const int tid = threadIdx.x, lane = tid & 31, wid = tid >> 5;
    const int warp_m = wid & 3, warp_n = wid >> 2;       // 4 x 2
    const int m0 = blockIdx.y * 128, n0 = blockIdx.x * 64;
    const long z = blockIdx.z;
    Ah += z * aZ; Al += z * aZ; Bh += z * bZ; Bl += z * bZ;
    const long coff = z * cZ;
    const float* bp = bias ? bias + z * biasZ : nullptr;

    float acc[2][4][4];
#pragma unroll
    for (int i = 0; i < 2; i++)
#pragma unroll
        for (int j = 0; j < 4; j++)
#pragma unroll
            for (int q = 0; q < 4; q++) acc[i][j][q] = 0.f;

    const int nc = K >> 6;

    auto load_chunk = [&](int c, int buf) {
        const int kk = c << 6;
        const uint32_t base = sb + buf * MBUF;
#pragma unroll
        for (int it = 0; it < 4; it++) {
            int idx = tid + it * 256;
            int row = idx >> 3, g = idx & 7;
            uint32_t d = base + SWZ(row*128 + g*16);
            long off = (long)(m0 + row) * lda + kk + g*8;
            cpasync16(d,       Ah + off);
            cpasync16(d + ATB, Al + off);
        }
#pragma unroll
        for (int it = 0; it < 2; it++) {
            int idx = tid + it * 256;
            int row = idx >> 3, g = idx & 7;
            uint32_t d = base + 2*ATB + SWZ(row*128 + g*16);
            long off = (long)(n0 + row) * ldb + kk + g*8;
            cpasync16(d,       Bh + off);
            cpasync16(d + BTB, Bl + off);
        }
        asm volatile("cp.async.commit_group;");
    };

    load_chunk(0, 0);

    const int rA  = warp_m*32 + (lane & 7) + ((lane >> 3) & 1)*8;   // + i*16
    const int cAb = ((lane >> 4) & 1) * 16;                          // + ks*32
    // B paired ldsm4: lanes 0-15 -> block 2*j2 (k-lo/k-hi), lanes 16-31 -> block 2*j2+1
    const int rB4 = warp_n*32 + ((lane >> 4) & 1)*8 + (lane & 7);    // + j2*16
    const int cBb = ((lane >> 3) & 1) * 16;                          // + ks*32

    for (int c = 0; c < nc; c++) {
        const int buf = c & 1;
        if (c + 1 < nc) load_chunk(c + 1, buf ^ 1);
        if (c + 1 < nc) asm volatile("cp.async.wait_group 1;");
        else            asm volatile("cp.async.wait_group 0;");
        __syncthreads();

        const uint32_t ab  = sb + buf * MBUF;
        const uint32_t alb = ab + ATB, bhb = ab + 2*ATB, blb = ab + 2*ATB + BTB;
#pragma unroll
        for (int ks = 0; ks < 4; ks++) {
            uint32_t ah[2][4], al[2][4], bh[4][2], bl[4][2];
#pragma unroll
            for (int i = 0; i < 2; i++) {
                uint32_t o = SWZ((rA + i*16)*128 + ks*32 + cAb);
                ldsm4(ah[i], ab + o);
                ldsm4(al[i], alb + o);
            }
#pragma unroll
            for (int j2 = 0; j2 < 2; j2++) {
                uint32_t o = SWZ((rB4 + j2*16)*128 + ks*32 + cBb);
                ldsm4(&bh[2*j2][0], bhb + o);
                ldsm4(&bl[2*j2][0], blb + o);
            }
#pragma unroll
            for (int i = 0; i < 2; i++)
#pragma unroll
                for (int j = 0; j < 4; j++) {
                    mma16816(acc[i][j], ah[i], bh[j]);
                    mma16816(acc[i][j], al[i], bh[j]);
                    mma16816(acc[i][j], ah[i], bl[j]);
                }
        }
        __syncthreads();
    }

#pragma unroll
    for (int i = 0; i < 2; i++) {
        int m = m0 + warp_m*32 + i*16 + (lane >> 2);
#pragma unroll
        for (int j = 0; j < 4; j++) {
            int n = n0 + warp_n*32 + j*8 + (lane & 3)*2;
            float b0v = bp ? bp[n] : 0.f, b1v = bp ? bp[n+1] : 0.f;
            float r0 = acc[i][j][0]*alpha + b0v, r1 = acc[i][j][1]*alpha + b1v;
            float r2 = acc[i][j][2]*alpha + b0v, r3 = acc[i][j][3]*alpha + b1v;
            if (relu) { r0=fmaxf(r0,0.f); r1=fmaxf(r1,0.f); r2=fmaxf(r2,0.f); r3=fmaxf(r3,0.f); }
            long o0 = coff + (long)m*ldc + n, o1 = coff + (long)(m+8)*ldc + n;
            if (HASC) {
                *(float2*)(C + o0) = make_float2(r0, r1);
                *(float2*)(C + o1) = make_float2(r2, r3);
            }
            if (HASB) {
                st_hilo(Chi, Clo, o0, r0, r1);
                st_hilo(Chi, Clo, o1, r2, r3);
            }
        }
    }
}

// ---------------- host orchestration ----------------
static __nv_bfloat16 *xh,*xl,*w1h,*w1l,*w2h,*w2l;
static __nv_bfloat16 *wq1h,*wq1l,*wk1h,*wk1l,*wo1h,*wo1l,*wa1h,*wa1l;
static __nv_bfloat16 *wq2h,*wq2l,*wk2h,*wk2l,*wo2h,*wo2l,*wa2h,*wa2l;
static __nv_bfloat16 *hh,*hl,*h2h,*h2l,*qh,*ql,*kh,*kl,*vth,*vtl,*cch,*ccl,*Ph,*Pl;
static float *h,*att,*S,*B1,*B2,*pP;

static cudaStream_t sA, sB;
static cudaEvent_t EV[12];
static bool g_init = false;

static inline void do_split(const float* s, __nv_bfloat16* hi, __nv_bfloat16* lo, long n,
                            cudaStream_t st) {
    long n4 = n >> 2;
    int grid = (int)((n4 + 255) / 256); if (grid > 4096) grid = 4096;
    splitk<<<grid, 256, 0, st>>>(s, hi, lo, n4);
}

struct BlkW {
    __nv_bfloat16 *qh,*ql,*kh,*kl,*oh,*ol,*ah,*al;
    const float *bq,*bk,*bo,*ba;
    const float* biasLog;
};

static void relation_block(const BlkW& W, float* outC, __nv_bfloat16* outHi, __nv_bfloat16* outLo,
                           cudaEvent_t eH, cudaEvent_t eK, cudaEvent_t eV)
{
    cudaEventRecord(eH, 0);
    cudaStreamWaitEvent(sA, eH, 0);
    cudaStreamWaitEvent(sB, eH, 0);
    mmag<false,true><<<dim3(16,8,1),256,MSMEM,0>>>(hh,hl,DD,0, W.qh,W.ql,DD,0,
                                       nullptr,qh,ql, DD,0, DD,1.f, W.bq,0,0);
    mmag<false,true><<<dim3(16,8,1),256,MSMEM,sA>>>(hh,hl,DD,0, W.kh,W.kl,DD,0,
                                        nullptr,kh,kl, DD,0, DD,1.f, W.bk,0,0);
    cudaEventRecord(eK, sA);
    mmag<false,true><<<dim3(16,8,1),256,MSMEM,sB>>>(W.oh,W.ol,DD,0, hh,hl,DD,0,
                                        nullptr,vth,vtl, RR,0, DD,1.f, nullptr,0,0);
    cudaEventRecord(eV, sB);
    // S[g] = 0.125 * Q_g K_g^T  (fp32)
    cudaStreamWaitEvent(0, eK, 0);
    mmag<true,false><<<dim3(16,8,GG),256,MSMEM,0>>>(qh,ql,DD,DGB, kh,kl,DD,DGB,
                                        S,nullptr,nullptr, RR,(long)RR*RR, DGB,0.125f, nullptr,0,0);
    cudaStreamWaitEvent(0, EV[1], 0);
    softmax_kernel<<<dim3(RR,GG),256,0,0>>>(S, W.biasLog, Ph, Pl);
    cudaStreamWaitEvent(0, eV, 0);
    mmag<true,false><<<dim3(1,8,GG),256,MSMEM,0>>>(Ph,Pl,RR,(long)RR*RR, vth,vtl,RR,(long)DGB*RR,
                                       att,nullptr,nullptr, DD,DGB, RR,1.f, W.bo,DGB,0);
    catsplit<<<(RR*3*DD/4)/256, 256, 0, 0>>>(h, att, cch, ccl);
    // concat GEMM split-K=2 (K=3072 -> 2x1536), then fused reduce+bias+relu
    mmag<true,false><<<dim3(16,8,2),256,MSMEM,0>>>(cch,ccl,3*DD,1536, W.ah,W.al,3*DD,1536,
                                       pP,nullptr,nullptr, DD,(long)RR*DD, 1536,1.f, nullptr,0,0);
    if (outC)
        reduce2<true,false,true><<<RR*DD/4/256, 256, 0, 0>>>(pP, W.ba, outC, nullptr, nullptr);
    else
        reduce2<false,true,true><<<RR*DD/4/256, 256, 0, 0>>>(pP, W.ba, nullptr, outHi, outLo);
}

extern "C" void kernel_launch(void* const* d_in, const int* in_sizes, int n_in,
                              void* d_out, int out_size)
{
    const float* x    = (const float*)d_in[0];
    const float* pe   = (const float*)d_in[1];
    const float* Wfc1 = (const float*)d_in[2];  const float* bfc1 = (const float*)d_in[3];
    const float* Wfc2 = (const float*)d_in[4];  const float* bfc2 = (const float*)d_in[5];
    const float* Wp1  = (const float*)d_in[6];  const float* bp1  = (const float*)d_in[7];
    const float* Wq1  = (const float*)d_in[8];  const float* bq1  = (const float*)d_in[9];
    const float* Wk1  = (const float*)d_in[10]; const float* bk1  = (const float*)d_in[11];
    const float* Wo1  = (const float*)d_in[12]; const float* bo1  = (const float*)d_in[13];
    const float* Wa1  = (const float*)d_in[14]; const float* ba1  = (const float*)d_in[15];
    const float* Wp2  = (const float*)d_in[16]; const float* bp2  = (const float*)d_in[17];
    const float* Wq2  = (const float*)d_in[18]; const float* bq2  = (const float*)d_in[19];
    const float* Wk2  = (const float*)d_in[20]; const float* bk2  = (const float*)d_in[21];
    const float* Wo2  = (const float*)d_in[22]; const float* bo2  = (const float*)d_in[23];
    const float* Wa2  = (const float*)d_in[24]; const float* ba2  = (const float*)d_in[25];
    float* out = (float*)d_out;

    if (!g_init) {
        cudaStreamCreateWithFlags(&sA, cudaStreamNonBlocking);
        cudaStreamCreateWithFlags(&sB, cudaStreamNonBlocking);
        for (int i = 0; i < 12; i++) cudaEventCreateWithFlags(&EV[i], cudaEventDisableTiming);
        g_init = true;
    }

    cudaFuncSetAttribute(mmag<true,true>,   cudaFuncAttributeMaxDynamicSharedMemorySize, MSMEM);
    cudaFuncSetAttribute(mmag<false,true>,  cudaFuncAttributeMaxDynamicSharedMemorySize, MSMEM);
    cudaFuncSetAttribute(mmag<true,false>,  cudaFuncAttributeMaxDynamicSharedMemorySize, MSMEM);

    cudaGetSymbolAddress((void**)&h, g_h);     cudaGetSymbolAddress((void**)&att, g_att);
    cudaGetSymbolAddress((void**)&S, g_S);     cudaGetSymbolAddress((void**)&pP, g_p);
    cudaGetSymbolAddress((void**)&B1, g_B1);   cudaGetSymbolAddress((void**)&B2, g_B2);
    cudaGetSymbolAddress((void**)&xh, g_xh);   cudaGetSymbolAddress((void**)&xl, g_xl);
    cudaGetSymbolAddress((void**)&w1h, g_w1h); cudaGetSymbolAddress((void**)&w1l, g_w1l);
    cudaGetSymbolAddress((void**)&w2h, g_w2h); cudaGetSymbolAddress((void**)&w2l, g_w2l);
    cudaGetSymbolAddress((void**)&wq1h, g_wq1h); cudaGetSymbolAddress((void**)&wq1l, g_wq1l);
    cudaGetSymbolAddress((void**)&wk1h, g_wk1h); cudaGetSymbolAddress((void**)&wk1l, g_wk1l);
    cudaGetSymbolAddress((void**)&wo1h, g_wo1h); cudaGetSymbolAddress((void**)&wo1l, g_wo1l);
    cudaGetSymbolAddress((void**)&wa1h, g_wa1h); cudaGetSymbolAddress((void**)&wa1l, g_wa1l);
    cudaGetSymbolAddress((void**)&wq2h, g_wq2h); cudaGetSymbolAddress((void**)&wq2l, g_wq2l);
    cudaGetSymbolAddress((void**)&wk2h, g_wk2h); cudaGetSymbolAddress((void**)&wk2l, g_wk2l);
    cudaGetSymbolAddress((void**)&wo2h, g_wo2h); cudaGetSymbolAddress((void**)&wo2l, g_wo2l);
    cudaGetSymbolAddress((void**)&wa2h, g_wa2h); cudaGetSymbolAddress((void**)&wa2l, g_wa2l);
    cudaGetSymbolAddress((void**)&hh, g_hh);   cudaGetSymbolAddress((void**)&hl, g_hl);
    cudaGetSymbolAddress((void**)&h2h, g_h2h); cudaGetSymbolAddress((void**)&h2l, g_h2l);
    cudaGetSymbolAddress((void**)&qh, g_qh);   cudaGetSymbolAddress((void**)&ql, g_ql);
    cudaGetSymbolAddress((void**)&kh, g_kh);   cudaGetSymbolAddress((void**)&kl, g_kl);
    cudaGetSymbolAddress((void**)&vth, g_vth); cudaGetSymbolAddress((void**)&vtl, g_vtl);
    cudaGetSymbolAddress((void**)&cch, g_cch); cudaGetSymbolAddress((void**)&ccl, g_ccl);
    cudaGetSymbolAddress((void**)&Ph, g_Ph);   cudaGetSymbolAddress((void**)&Pl, g_Pl);

    // ---- fork ----
    cudaEventRecord(EV[0], 0);
    cudaStreamWaitEvent(sA, EV[0], 0);
    cudaStreamWaitEvent(sB, EV[0], 0);

    // sA: position bias (memory-bound, overlaps fc1)
    posbias_kernel<<<dim3(RR, RR/128), 128, 0, sA>>>(pe, Wp1, bp1, Wp2, bp2, B1, B2);
    cudaEventRecord(EV[1], sA);

    // sB: splits — x+Wfc1 first (fc1 gate), then remaining weights
    do_split(x, xh, xl, (long)RR*KFC1, sB);
    do_split(Wfc1, w1h, w1l, (long)DD*KFC1, sB);
    cudaEventRecord(EV[2], sB);
    do_split(Wq1, wq1h, wq1l, (long)DD*DD, sB);
    do_split(Wk1, wk1h, wk1l, (long)DD*DD, sB);
    do_split(Wo1, wo1h, wo1l, (long)DD*DD, sB);
    do_split(Wa1, wa1h, wa1l, (long)DD*3*DD, sB);
    do_split(Wfc2, w2h, w2l, (long)DD*DD, sB);
    do_split(Wq2, wq2h, wq2l, (long)DD*DD, sB);
    do_split(Wk2, wk2h, wk2l, (long)DD*DD, sB);
    do_split(Wo2, wo2h, wo2l, (long)DD*DD, sB);
    do_split(Wa2, wa2h, wa2l, (long)DD*3*DD, sB);
    cudaEventRecord(EV[3], sB);

    // stream 0: fc1 split-K=2 after x/Wfc1 splits, then reduce + split
    cudaStreamWaitEvent(0, EV[2], 0);
    mmag<true,false><<<dim3(16,8,2),256,MSMEM,0>>>(xh,xl,KFC1,KHALF, w1h,w1l,KFC1,KHALF,
                                       pP,nullptr,nullptr, DD,(long)RR*DD, KHALF,1.f, nullptr,0,0);
    reduce2<true,true,false><<<RR*DD/4/256, 256, 0, 0>>>(pP, bfc1, h, hh, hl);

    cudaStreamWaitEvent(0, EV[3], 0);
    cudaStreamWaitEvent(sA, EV[3], 0);
    cudaStreamWaitEvent(sB, EV[3], 0);

    // relation block 1 -> h2 (bf16 only)
    BlkW W1b = { wq1h,wq1l, wk1h,wk1l, wo1h,wo1l, wa1h,wa1l, bq1,bk1,bo1,ba1, B1 };
    relation_block(W1b, nullptr, h2h, h2l, EV[4], EV[5], EV[6]);

    // fc2 split-K=2: h = h2 @ Wfc2^T + bfc2
    mmag<true,false><<<dim3(16,8,2),256,MSMEM,0>>>(h2h,h2l,DD,512, w2h,w2l,DD,512,
                                       pP,nullptr,nullptr, DD,(long)RR*DD, 512,1.f, nullptr,0,0);
    reduce2<true,true,false><<<RR*DD/4/256, 256, 0, 0>>>(pP, bfc2, h, hh, hl);

    // relation block 2 -> out (fp32)
    BlkW W2b = { wq2h,wq2l, wk2h,wk2l, wo2h,wo2l, wa2h,wa2l, bq2,bk2,bo2,ba2, B2 };
    relation_block(W2b, out, nullptr, nullptr, EV[7], EV[8], EV[9]);
}